// round 9
// baseline (speedup 1.0000x reference)
#include <cuda_runtime.h>
#include <math.h>
#include <stdint.h>

// Problem constants
#define BB   128
#define NN   256
#define DIN  128
#define HH   8
#define DK   16
#define HK   128
#define ROWS (BB*NN)        // 32768
#define NORMC 0.25f
#define AS   132            // GEMM A smem stride
#define SPS  257            // score/prob row stride (odd => conflict-free)
#define RST  17             // red row stride (odd)
#define PLANE ((size_t)BB * NN * NN)   // 8,388,608 per head

// ---------------- device-global scratch ----------------
// Q/K/V head-major: [h][b*N+n][16]
__device__ float g_Q[(size_t)HH * ROWS * DK];
__device__ float g_K[(size_t)HH * ROWS * DK];
__device__ float g_V[(size_t)HH * ROWS * DK];
__device__ float g_heads[(size_t)ROWS * HK];

__device__ float g_breaks[512];
__device__ float g_tab[512 * 16];
__device__ float g_bias[(size_t)HH * PLANE];   // 256 MB: bias[h][b][i][j], -inf when masked

// =====================================================================
// PWL build (one block, 512 threads)
// =====================================================================
__global__ void pwl_build_kernel(const float* __restrict__ mw1, const float* __restrict__ mb1,
                                 const float* __restrict__ mw2, const float* __restrict__ mb2,
                                 const float* __restrict__ mw3, const float* __restrict__ mb3)
{
    __shared__ float w1[16], b1[16], w2[256], b2[16], w3[128], b3[8];
    __shared__ float tsort[16];
    __shared__ float cand[512];
    __shared__ int   cnt;

    const int tid = threadIdx.x;
    if (tid < 16)  { w1[tid] = mw1[tid]; b1[tid] = mb1[tid]; b2[tid] = mb2[tid]; }
    if (tid < 256) w2[tid] = mw2[tid];
    if (tid < 128) w3[tid] = mw3[tid];
    if (tid < 8)   b3[tid] = mb3[tid];
    cand[tid] = 3.0e38f;
    if (tid == 0) cnt = 16;
    __syncthreads();

    if (tid < 16) {
        float t = (w1[tid] != 0.f) ? (-b1[tid] / w1[tid]) : 3.0e38f;
        cand[tid] = t;
    }
    __syncthreads();
    if (tid == 0) {
        for (int i = 0; i < 16; i++) tsort[i] = cand[i];
        for (int i = 1; i < 16; i++) {
            float v = tsort[i]; int k = i - 1;
            while (k >= 0 && tsort[k] > v) { tsort[k + 1] = tsort[k]; k--; }
            tsort[k + 1] = v;
        }
    }
    __syncthreads();

    if (tid < 17 * 16) {
        int iv = tid >> 4, c = tid & 15;
        float lo = (iv == 0)  ? -3.0e38f : tsort[iv - 1];
        float hi = (iv == 16) ?  3.0e38f : tsort[iv];
        if (lo < hi) {
            float m;
            if (lo <= -1e30f && hi >= 1e30f) m = 0.f;
            else if (lo <= -1e30f)           m = hi - 1.f;
            else if (hi >=  1e30f)           m = lo + 1.f;
            else                             m = 0.5f * (lo + hi);
            float g = 0.f, q = b2[c];
            for (int n = 0; n < 16; n++) {
                if (fmaf(m, w1[n], b1[n]) > 0.f) {
                    g = fmaf(w1[n], w2[n * 16 + c], g);
                    q = fmaf(b1[n], w2[n * 16 + c], q);
                }
            }
            if (g != 0.f) {
                float x = -q / g;
                if (x > lo && x < hi && fabsf(x) < 1e30f) {
                    int k = atomicAdd(&cnt, 1);
                    cand[k] = x;
                }
            }
        }
    }
    __syncthreads();
    const int ncand = cnt;

    for (int k = 2; k <= 512; k <<= 1) {
        for (int j = k >> 1; j > 0; j >>= 1) {
            int ixj = tid ^ j;
            if (ixj > tid) {
                bool up = (tid & k) == 0;
                float a = cand[tid], b = cand[ixj];
                if ((a > b) == up) { cand[tid] = b; cand[ixj] = a; }
            }
            __syncthreads();
        }
    }

    g_breaks[tid] = (tid < ncand) ? cand[tid] : 3.0e38f;

    if (tid <= ncand) {
        float lo = (tid == 0)     ? -3.0e38f : cand[tid - 1];
        float hi = (tid == ncand) ?  3.0e38f : cand[tid];
        float m;
        if (lo <= -1e30f && hi >= 1e30f) m = 0.f;
        else if (lo <= -1e30f)           m = hi - 1.f;
        else if (hi >=  1e30f)           m = lo + 1.f;
        else                             m = 0.5f * (lo + hi);

        float slope[8], inter[8];
        for (int h = 0; h < 8; h++) { slope[h] = 0.f; inter[h] = b3[h]; }
        for (int c = 0; c < 16; c++) {
            float gc = 0.f, qc = b2[c];
            for (int n = 0; n < 16; n++) {
                if (fmaf(m, w1[n], b1[n]) > 0.f) {
                    gc = fmaf(w1[n], w2[n * 16 + c], gc);
                    qc = fmaf(b1[n], w2[n * 16 + c], qc);
                }
            }
            if (fmaf(gc, m, qc) > 0.f) {
                for (int h = 0; h < 8; h++) {
                    slope[h] = fmaf(gc, w3[c * 8 + h], slope[h]);
                    inter[h] = fmaf(qc, w3[c * 8 + h], inter[h]);
                }
            }
        }
        for (int h = 0; h < 8; h++) {
            g_tab[tid * 16 + h * 2]     = slope[h];
            g_tab[tid * 16 + h * 2 + 1] = inter[h];
        }
    }
}

// =====================================================================
// bias kernel: per (b,i,j) binary search + 8 head biases -> g_bias.
// Mask folded as -inf. DRAM-bound (~335MB traffic).
// grid 4096 x 512 threads, one float4/int4 per thread.
// =====================================================================
__global__ void __launch_bounds__(512) bias_kernel(const float* __restrict__ Ebm,
                                                   const int* __restrict__ mask)
{
    __shared__ float sB[512];
    __shared__ float sT[512 * 16];
    const int tid = threadIdx.x;
    sB[tid] = g_breaks[tid];
#pragma unroll
    for (int i = 0; i < 16; i++) sT[tid + 512 * i] = g_tab[tid + 512 * i];
    __syncthreads();

    const size_t v = (size_t)blockIdx.x * 512 + tid;   // vec4 index
    float4 e4 = ((const float4*)Ebm)[v];
    int4   m4 = ((const int4*)mask)[v];
    const float ev[4] = {e4.x, e4.y, e4.z, e4.w};
    const int   mv[4] = {m4.x, m4.y, m4.z, m4.w};

    float out[8][4];
#pragma unroll
    for (int p = 0; p < 4; p++) {
        float e = ev[p];
        int seg = 0;
#pragma unroll
        for (int st = 256; st >= 1; st >>= 1) {
            int c = seg + st;
            if (e >= sB[c - 1]) seg = c;
        }
        const float* tp = sT + seg * 16;
        if (mv[p]) {
#pragma unroll
            for (int h = 0; h < 8; h++) out[h][p] = -INFINITY;
        } else {
#pragma unroll
            for (int h = 0; h < 8; h++) out[h][p] = fmaf(tp[2 * h], e, tp[2 * h + 1]);
        }
    }
#pragma unroll
    for (int h = 0; h < 8; h++)
        *(float4*)(g_bias + (size_t)h * PLANE + v * 4) =
            make_float4(out[h][0], out[h][1], out[h][2], out[h][3]);
}

// =====================================================================
// GEMM body (as R7)
// =====================================================================
__device__ __forceinline__ void gemm_body(const float* __restrict__ A,
                                          const float* __restrict__ Wraw,
                                          float* __restrict__ Out,
                                          int mode, int row0)
{
    extern __shared__ float sm[];
    float* Wsm = sm;
    float* Asm = sm + 128 * 128;

    const int tid = threadIdx.x;

    for (int i4 = tid; i4 < 4096; i4 += 256) {
        int d = i4 >> 5, c4 = (i4 & 31) * 4;
        float4 w;
        if (mode == 0) w = *(const float4*)(Wraw + (c4 >> 4) * (DIN * 16) + d * 16 + (c4 & 15));
        else           w = *(const float4*)(Wraw + d * 128 + c4);
        *(float4*)(Wsm + d * 128 + c4) = w;
    }
    for (int i4 = tid; i4 < 2048; i4 += 256) {
        int r = i4 >> 5, c4 = (i4 & 31) * 4;
        *(float4*)(Asm + r * AS + c4) = *(const float4*)(A + (size_t)(row0 + r) * 128 + c4);
    }
    __syncthreads();

    const int tx = tid & 15, ty = tid >> 4;
    const int ca = tx * 4;
    const int r0 = ty * 4;
    float acc[4][8];
#pragma unroll
    for (int u = 0; u < 4; u++)
#pragma unroll
        for (int k = 0; k < 8; k++) acc[u][k] = 0.f;

#pragma unroll 2
    for (int dc = 0; dc < 128; dc += 4) {
        float4 a4[4];
#pragma unroll
        for (int u = 0; u < 4; u++) a4[u] = *(const float4*)(Asm + (r0 + u) * AS + dc);
#pragma unroll
        for (int dd = 0; dd < 4; dd++) {
            float4 w0 = *(const float4*)(Wsm + (dc + dd) * 128 + ca);
            float4 w1 = *(const float4*)(Wsm + (dc + dd) * 128 + 64 + ca);
            float wv[8] = {w0.x, w0.y, w0.z, w0.w, w1.x, w1.y, w1.z, w1.w};
#pragma unroll
            for (int u = 0; u < 4; u++) {
                float a = (dd == 0) ? a4[u].x : (dd == 1) ? a4[u].y : (dd == 2) ? a4[u].z : a4[u].w;
#pragma unroll
                for (int k = 0; k < 8; k++) acc[u][k] = fmaf(a, wv[k], acc[u][k]);
            }
        }
    }
#pragma unroll
    for (int u = 0; u < 4; u++) {
        float4 o0 = {acc[u][0], acc[u][1], acc[u][2], acc[u][3]};
        float4 o1 = {acc[u][4], acc[u][5], acc[u][6], acc[u][7]};
        const int row = row0 + r0 + u;
        if (mode == 0) {
            int h0 = ca >> 4, h1 = (64 + ca) >> 4;
            *(float4*)(Out + ((size_t)h0 * ROWS + row) * 16 + (ca & 15)) = o0;
            *(float4*)(Out + ((size_t)h1 * ROWS + row) * 16 + (ca & 15)) = o1;
        } else {
            float* orow = Out + (size_t)row * 128;
            *(float4*)(orow + ca)      = o0;
            *(float4*)(orow + 64 + ca) = o1;
        }
    }
}

__global__ void __launch_bounds__(256) gemm_qkv_kernel(const float* __restrict__ q,
                                                       const float* __restrict__ hx,
                                                       const float* __restrict__ Wq,
                                                       const float* __restrict__ Wk,
                                                       const float* __restrict__ Wv)
{
    const int z = blockIdx.y;
    const float* A = (z == 0) ? q : hx;
    const float* W = (z == 0) ? Wq : (z == 1) ? Wk : Wv;
    float* Out = (z == 0) ? g_Q : (z == 1) ? g_K : g_V;
    gemm_body(A, W, Out, 0, blockIdx.x * 64);
}

__global__ void __launch_bounds__(256) gemm_out_kernel(const float* __restrict__ Wo,
                                                       float* __restrict__ Out)
{
    gemm_body(g_heads, Wo, Out, 1, blockIdx.x * 64);
}

// =====================================================================
// Fused attention v5: bias precomputed in global; no P0; softmax in place.
// Block = (b, 32-row tile, head). 512 threads, 2 blocks/SM.
// smem (floats): SP 32x257=8224 | red 16x32x17=8704 | V 4096 | Q 512
//                total 21536 f = 86,144 B
// =====================================================================
__global__ void __launch_bounds__(512, 2)
attn_fused_kernel()
{
    extern __shared__ float sm[];
    float* SP  = sm;                 // [32][257] scores -> probs (in place)
    float* red = SP + 8224;          // [16][32][17]
    float* sV  = red + 8704;         // [256][16]
    float* Qsm = sV + 4096;          // [32][16] (pre-scaled by NORMC)

    const int tid   = threadIdx.x;
    const int b     = blockIdx.y;
    const int itile = (blockIdx.x & 7) * 32;
    const int head  = blockIdx.x >> 3;

    const size_t hbase = (size_t)head * ROWS + (size_t)b * NN;

    const int warp = tid >> 5, lane = tid & 31;
    const int jq8 = warp & 7;
    const int jgl = jq8 * 32 + lane;
    const int rh  = warp >> 3;

    // ---- K straight from global into registers
    float K0[16];
    {
        const float4* Kg = (const float4*)(g_K + (hbase + jgl) * 16);
#pragma unroll
        for (int qq = 0; qq < 4; qq++) *(float4*)(K0 + 4 * qq) = Kg[qq];
    }

    // ---- stage V (contiguous), Q (scaled)
    {
        const float4* Vg = (const float4*)(g_V + hbase * 16);
#pragma unroll
        for (int p = 0; p < 2; p++) {
            int q4 = tid + 512 * p;
            *(float4*)(sV + q4 * 4) = Vg[q4];
        }
        if (tid < 128) {
            float4 qv = *(const float4*)(g_Q + (hbase + itile) * 16 + tid * 4);
            qv.x *= NORMC; qv.y *= NORMC; qv.z *= NORMC; qv.w *= NORMC;
            *(float4*)(Qsm + tid * 4) = qv;
        }
    }
    __syncthreads();

    // ---- P1: SP = bias + Q.K  (bias LDG coalesced; K regs; rows rh*16..+15)
    {
        const float* bp = g_bias + (size_t)head * PLANE
                        + ((size_t)(b * NN + itile)) * NN + jgl;
        const int rbase = rh * 16;
#pragma unroll 4
        for (int rr = 0; rr < 16; rr++) {
            const int r = rbase + rr;
            const float* qp = Qsm + r * 16;
            float4 q0 = *(const float4*)(qp);
            float4 q1 = *(const float4*)(qp + 4);
            float4 q2 = *(const float4*)(qp + 8);
            float4 q3 = *(const float4*)(qp + 12);
            float d = 0.f;
            d = fmaf(q0.x, K0[0], d);  d = fmaf(q0.y, K0[1], d);
            d = fmaf(q0.z, K0[2], d);  d = fmaf(q0.w, K0[3], d);
            d = fmaf(q1.x, K0[4], d);  d = fmaf(q1.y, K0[5], d);
            d = fmaf(q1.z, K0[6], d);  d = fmaf(q1.w, K0[7], d);
            d = fmaf(q2.x, K0[8], d);  d = fmaf(q2.y, K0[9], d);
            d = fmaf(q2.z, K0[10], d); d = fmaf(q2.w, K0[11], d);
            d = fmaf(q3.x, K0[12], d); d = fmaf(q3.y, K0[13], d);
            d = fmaf(q3.z, K0[14], d); d = fmaf(q3.w, K0[15], d);
            SP[r * SPS + jgl] = bp[(size_t)r * NN] + d;   // -inf + d = -inf
        }
    }
    __syncthreads();

    // ---- P2: softmax per row, in place (warp = 2 rows; conflict-free strided)
    {
#pragma unroll
        for (int rr = 0; rr < 2; rr++) {
            const int r = warp * 2 + rr;
            float v[8];
#pragma unroll
            for (int m = 0; m < 8; m++) v[m] = SP[r * SPS + lane + 32 * m];
            float mx = v[0];
#pragma unroll
            for (int m = 1; m < 8; m++) mx = fmaxf(mx, v[m]);
#pragma unroll
            for (int o = 16; o > 0; o >>= 1) mx = fmaxf(mx, __shfl_xor_sync(0xffffffffu, mx, o));
            float s = 0.f;
#pragma unroll
            for (int m = 0; m < 8; m++) { v[m] = __expf(v[m] - mx); s += v[m]; }
#pragma unroll
            for (int o = 16; o > 0; o >>= 1) s += __shfl_xor_sync(0xffffffffu, s, o);
            float inv = 1.f / s;
#pragma unroll
            for (int m = 0; m < 8; m++) SP[r * SPS + lane + 32 * m] = v[m] * inv;
        }
    }
    __syncthreads();

    // ---- P3: AV. warp = 16-j group; lane = row. conflict-free p loads.
    {
        const int j0 = warp * 16;
        float acc[16];
#pragma unroll
        for (int v = 0; v < 16; v++) acc[v] = 0.f;
#pragma unroll
        for (int jj = 0; jj < 16; jj++) {
            const int j = j0 + jj;
            float p = SP[lane * SPS + j];                      // (lane+j)%32 distinct
            const float4* vp = (const float4*)(sV + j * 16);   // broadcast
            float4 v0 = vp[0], v1 = vp[1], v2 = vp[2], v3 = vp[3];
            acc[0]  = fmaf(p, v0.x, acc[0]);  acc[1]  = fmaf(p, v0.y, acc[1]);
            acc[2]  = fmaf(p, v0.z, acc[2]);  acc[3]  = fmaf(p, v0.w, acc[3]);
            acc[4]  = fmaf(p, v1.x, acc[4]);  acc[5]  = fmaf(p, v1.y, acc[5]);
            acc[6]  = fmaf(p, v1.z, acc[6]);  acc[7]  = fmaf(p, v1.w, acc[7]);
            acc[8]  = fmaf(p, v2.x, acc[8]);  acc[9]  = fmaf(p, v2.y, acc[9]);
            acc[10] = fmaf(p, v2.z, acc[10]); acc[11] = fmaf(p, v2.w, acc[11]);
            acc[12] = fmaf(p, v3.x, acc[12]); acc[13] = fmaf(p, v3.y, acc[13]);
            acc[14] = fmaf(p, v3.z, acc[14]); acc[15] = fmaf(p, v3.w, acc[15]);
        }
        float* rp = red + (warp * 32 + lane) * RST;
#pragma unroll
        for (int v = 0; v < 16; v++) rp[v] = acc[v];           // stride 17, conflict-free
    }
    __syncthreads();

    // ---- P4: sum 16 j-group partials, write g_heads
    {
        const int r = tid >> 4, v = tid & 15;
        float s = 0.f;
#pragma unroll
        for (int jq = 0; jq < 16; jq++)
            s += red[(jq * 32 + r) * RST + v];
        g_heads[(size_t)(b * NN + itile + r) * HK + head * 16 + v] = s;
    }
}

// =====================================================================
// host launcher
// =====================================================================
extern "C" void kernel_launch(void* const* d_in, const int* in_sizes, int n_in,
                              void* d_out, int out_size)
{
    (void)in_sizes; (void)n_in; (void)out_size;
    const float* q    = (const float*)d_in[0];
    const float* hx   = (const float*)d_in[1];
    const int*   mask = (const int*)d_in[2];
    const float* edge = (const float*)d_in[3];
    const float* Wq   = (const float*)d_in[4];
    const float* Wk   = (const float*)d_in[5];
    const float* Wv   = (const float*)d_in[6];
    const float* Wo   = (const float*)d_in[7];
    const float* mw1  = (const float*)d_in[8];
    const float* mb1  = (const float*)d_in[9];
    const float* mw2  = (const float*)d_in[10];
    const float* mb2  = (const float*)d_in[11];
    const float* mw3  = (const float*)d_in[12];
    const float* mb3  = (const float*)d_in[13];

    const int smem_gemm = (128 * 128 + 64 * AS) * 4;
    const int smem_attn = 21536 * 4;   // 86,144 B

    cudaFuncSetAttribute(gemm_qkv_kernel,   cudaFuncAttributeMaxDynamicSharedMemorySize, smem_gemm);
    cudaFuncSetAttribute(gemm_out_kernel,   cudaFuncAttributeMaxDynamicSharedMemorySize, smem_gemm);
    cudaFuncSetAttribute(attn_fused_kernel, cudaFuncAttributeMaxDynamicSharedMemorySize, smem_attn);

    pwl_build_kernel<<<1, 512>>>(mw1, mb1, mw2, mb2, mw3, mb3);

    gemm_qkv_kernel<<<dim3(ROWS / 64, 3), 256, smem_gemm>>>(q, hx, Wq, Wk, Wv);

    // per-head bias planes (mask folded), replaces seg kernel
    bias_kernel<<<(BB * NN * NN) / (512 * 4), 512>>>(edge, mask);

    attn_fused_kernel<<<dim3(64, BB), 512, smem_attn>>>();

    gemm_out_kernel<<<ROWS / 64, 256, smem_gemm>>>(Wo, (float*)d_out);
}

// round 10
// speedup vs baseline: 1.0982x; 1.0982x over previous
#include <cuda_runtime.h>
#include <math.h>
#include <stdint.h>

// Problem constants
#define BB   128
#define NN   256
#define DIN  128
#define HH   8
#define DK   16
#define HK   128
#define ROWS (BB*NN)        // 32768
#define NORMC 0.25f
#define AS   132            // GEMM A smem stride
#define SPS  257            // score/prob row stride (odd => conflict-free)
#define RST  17             // red row stride (odd)

// ---------------- device-global scratch ----------------
// Q/K/V head-major: [h][b*N+n][16]
__device__ float g_Q[(size_t)HH * ROWS * DK];
__device__ float g_K[(size_t)HH * ROWS * DK];
__device__ float g_V[(size_t)HH * ROWS * DK];
__device__ float g_heads[(size_t)ROWS * HK];

__device__ float g_breaks[512];
__device__ float g_tab[512 * 16];
__device__ unsigned short g_seg[(size_t)BB * NN * NN]; // seg | mask<<15

// =====================================================================
// PWL build (one block, 512 threads)
// =====================================================================
__global__ void pwl_build_kernel(const float* __restrict__ mw1, const float* __restrict__ mb1,
                                 const float* __restrict__ mw2, const float* __restrict__ mb2,
                                 const float* __restrict__ mw3, const float* __restrict__ mb3)
{
    __shared__ float w1[16], b1[16], w2[256], b2[16], w3[128], b3[8];
    __shared__ float tsort[16];
    __shared__ float cand[512];
    __shared__ int   cnt;

    const int tid = threadIdx.x;
    if (tid < 16)  { w1[tid] = mw1[tid]; b1[tid] = mb1[tid]; b2[tid] = mb2[tid]; }
    if (tid < 256) w2[tid] = mw2[tid];
    if (tid < 128) w3[tid] = mw3[tid];
    if (tid < 8)   b3[tid] = mb3[tid];
    cand[tid] = 3.0e38f;
    if (tid == 0) cnt = 16;
    __syncthreads();

    if (tid < 16) {
        float t = (w1[tid] != 0.f) ? (-b1[tid] / w1[tid]) : 3.0e38f;
        cand[tid] = t;
    }
    __syncthreads();
    if (tid == 0) {
        for (int i = 0; i < 16; i++) tsort[i] = cand[i];
        for (int i = 1; i < 16; i++) {
            float v = tsort[i]; int k = i - 1;
            while (k >= 0 && tsort[k] > v) { tsort[k + 1] = tsort[k]; k--; }
            tsort[k + 1] = v;
        }
    }
    __syncthreads();

    if (tid < 17 * 16) {
        int iv = tid >> 4, c = tid & 15;
        float lo = (iv == 0)  ? -3.0e38f : tsort[iv - 1];
        float hi = (iv == 16) ?  3.0e38f : tsort[iv];
        if (lo < hi) {
            float m;
            if (lo <= -1e30f && hi >= 1e30f) m = 0.f;
            else if (lo <= -1e30f)           m = hi - 1.f;
            else if (hi >=  1e30f)           m = lo + 1.f;
            else                             m = 0.5f * (lo + hi);
            float g = 0.f, q = b2[c];
            for (int n = 0; n < 16; n++) {
                if (fmaf(m, w1[n], b1[n]) > 0.f) {
                    g = fmaf(w1[n], w2[n * 16 + c], g);
                    q = fmaf(b1[n], w2[n * 16 + c], q);
                }
            }
            if (g != 0.f) {
                float x = -q / g;
                if (x > lo && x < hi && fabsf(x) < 1e30f) {
                    int k = atomicAdd(&cnt, 1);
                    cand[k] = x;
                }
            }
        }
    }
    __syncthreads();
    const int ncand = cnt;

    for (int k = 2; k <= 512; k <<= 1) {
        for (int j = k >> 1; j > 0; j >>= 1) {
            int ixj = tid ^ j;
            if (ixj > tid) {
                bool up = (tid & k) == 0;
                float a = cand[tid], b = cand[ixj];
                if ((a > b) == up) { cand[tid] = b; cand[ixj] = a; }
            }
            __syncthreads();
        }
    }

    g_breaks[tid] = (tid < ncand) ? cand[tid] : 3.0e38f;

    if (tid <= ncand) {
        float lo = (tid == 0)     ? -3.0e38f : cand[tid - 1];
        float hi = (tid == ncand) ?  3.0e38f : cand[tid];
        float m;
        if (lo <= -1e30f && hi >= 1e30f) m = 0.f;
        else if (lo <= -1e30f)           m = hi - 1.f;
        else if (hi >=  1e30f)           m = lo + 1.f;
        else                             m = 0.5f * (lo + hi);

        float slope[8], inter[8];
        for (int h = 0; h < 8; h++) { slope[h] = 0.f; inter[h] = b3[h]; }
        for (int c = 0; c < 16; c++) {
            float gc = 0.f, qc = b2[c];
            for (int n = 0; n < 16; n++) {
                if (fmaf(m, w1[n], b1[n]) > 0.f) {
                    gc = fmaf(w1[n], w2[n * 16 + c], gc);
                    qc = fmaf(b1[n], w2[n * 16 + c], qc);
                }
            }
            if (fmaf(gc, m, qc) > 0.f) {
                for (int h = 0; h < 8; h++) {
                    slope[h] = fmaf(gc, w3[c * 8 + h], slope[h]);
                    inter[h] = fmaf(qc, w3[c * 8 + h], inter[h]);
                }
            }
        }
        for (int h = 0; h < 8; h++) {
            g_tab[tid * 16 + h * 2]     = slope[h];
            g_tab[tid * 16 + h * 2 + 1] = inter[h];
        }
    }
}

// =====================================================================
// seg kernel: per (b,i,j) binary-search segment; fold mask into bit 15
// =====================================================================
__global__ void __launch_bounds__(512) seg_kernel(const float* __restrict__ Ebm,
                                                  const int* __restrict__ mask)
{
    __shared__ float sB[512];
    const int tid = threadIdx.x;
    sB[tid] = g_breaks[tid];
    __syncthreads();

    const size_t v = (size_t)blockIdx.x * 512 + tid;
    float4 e4 = ((const float4*)Ebm)[v];
    int4   m4 = ((const int4*)mask)[v];
    ushort4 out;
    const float ev[4] = {e4.x, e4.y, e4.z, e4.w};
    const int   mv[4] = {m4.x, m4.y, m4.z, m4.w};
    unsigned short ov[4];
#pragma unroll
    for (int p = 0; p < 4; p++) {
        float e = ev[p];
        int seg = 0;
#pragma unroll
        for (int st = 256; st >= 1; st >>= 1) {
            int cnd = seg + st;
            if (e >= sB[cnd - 1]) seg = cnd;
        }
        ov[p] = (unsigned short)(seg | (mv[p] ? 0x8000 : 0));
    }
    out.x = ov[0]; out.y = ov[1]; out.z = ov[2]; out.w = ov[3];
    ((ushort4*)g_seg)[v] = out;
}

// =====================================================================
// GEMM body (as R7/R8)
// =====================================================================
__device__ __forceinline__ void gemm_body(const float* __restrict__ A,
                                          const float* __restrict__ Wraw,
                                          float* __restrict__ Out,
                                          int mode, int row0)
{
    extern __shared__ float sm[];
    float* Wsm = sm;
    float* Asm = sm + 128 * 128;

    const int tid = threadIdx.x;

    for (int i4 = tid; i4 < 4096; i4 += 256) {
        int d = i4 >> 5, c4 = (i4 & 31) * 4;
        float4 w;
        if (mode == 0) w = *(const float4*)(Wraw + (c4 >> 4) * (DIN * 16) + d * 16 + (c4 & 15));
        else           w = *(const float4*)(Wraw + d * 128 + c4);
        *(float4*)(Wsm + d * 128 + c4) = w;
    }
    for (int i4 = tid; i4 < 2048; i4 += 256) {
        int r = i4 >> 5, c4 = (i4 & 31) * 4;
        *(float4*)(Asm + r * AS + c4) = *(const float4*)(A + (size_t)(row0 + r) * 128 + c4);
    }
    __syncthreads();

    const int tx = tid & 15, ty = tid >> 4;
    const int ca = tx * 4;
    const int r0 = ty * 4;
    float acc[4][8];
#pragma unroll
    for (int u = 0; u < 4; u++)
#pragma unroll
        for (int k = 0; k < 8; k++) acc[u][k] = 0.f;

#pragma unroll 2
    for (int dc = 0; dc < 128; dc += 4) {
        float4 a4[4];
#pragma unroll
        for (int u = 0; u < 4; u++) a4[u] = *(const float4*)(Asm + (r0 + u) * AS + dc);
#pragma unroll
        for (int dd = 0; dd < 4; dd++) {
            float4 w0 = *(const float4*)(Wsm + (dc + dd) * 128 + ca);
            float4 w1 = *(const float4*)(Wsm + (dc + dd) * 128 + 64 + ca);
            float wv[8] = {w0.x, w0.y, w0.z, w0.w, w1.x, w1.y, w1.z, w1.w};
#pragma unroll
            for (int u = 0; u < 4; u++) {
                float a = (dd == 0) ? a4[u].x : (dd == 1) ? a4[u].y : (dd == 2) ? a4[u].z : a4[u].w;
#pragma unroll
                for (int k = 0; k < 8; k++) acc[u][k] = fmaf(a, wv[k], acc[u][k]);
            }
        }
    }
#pragma unroll
    for (int u = 0; u < 4; u++) {
        float4 o0 = {acc[u][0], acc[u][1], acc[u][2], acc[u][3]};
        float4 o1 = {acc[u][4], acc[u][5], acc[u][6], acc[u][7]};
        const int row = row0 + r0 + u;
        if (mode == 0) {
            int h0 = ca >> 4, h1 = (64 + ca) >> 4;
            *(float4*)(Out + ((size_t)h0 * ROWS + row) * 16 + (ca & 15)) = o0;
            *(float4*)(Out + ((size_t)h1 * ROWS + row) * 16 + (ca & 15)) = o1;
        } else {
            float* orow = Out + (size_t)row * 128;
            *(float4*)(orow + ca)      = o0;
            *(float4*)(orow + 64 + ca) = o1;
        }
    }
}

__global__ void __launch_bounds__(256) gemm_qkv_kernel(const float* __restrict__ q,
                                                       const float* __restrict__ hx,
                                                       const float* __restrict__ Wq,
                                                       const float* __restrict__ Wk,
                                                       const float* __restrict__ Wv)
{
    const int z = blockIdx.y;
    const float* A = (z == 0) ? q : hx;
    const float* W = (z == 0) ? Wq : (z == 1) ? Wk : Wv;
    float* Out = (z == 0) ? g_Q : (z == 1) ? g_K : g_V;
    gemm_body(A, W, Out, 0, blockIdx.x * 64);
}

__global__ void __launch_bounds__(256) gemm_out_kernel(const float* __restrict__ Wo,
                                                       float* __restrict__ Out)
{
    gemm_body(g_heads, Wo, Out, 1, blockIdx.x * 64);
}

// =====================================================================
// Fused attention v6: bias fused INTO P1 (no P0, no RMW), seg precomputed.
// Block = (b, 32-row tile, head). 512 threads, 2 blocks/SM.
// smem (floats): SP 32x257=8224 | red 16x32x17=8704 | V 4096 | Q 512
//                | sT 608  total 22144 f = 88,576 B
// =====================================================================
__global__ void __launch_bounds__(512, 2)
attn_fused_kernel(const float* __restrict__ Ebm)
{
    extern __shared__ float sm[];
    float* SP  = sm;                 // [32][257] scores -> probs (in place)
    float* red = SP + 8224;          // [16][32][17]
    float* sV  = red + 8704;         // [256][16]
    float* Qsm = sV + 4096;          // [32][16] (pre-scaled by NORMC)
    float* sT  = Qsm + 512;          // [304][2] slope/inter for this head

    const int tid   = threadIdx.x;
    const int b     = blockIdx.y;
    const int itile = (blockIdx.x & 7) * 32;
    const int head  = blockIdx.x >> 3;

    const size_t hbase = (size_t)head * ROWS + (size_t)b * NN;

    const int warp = tid >> 5, lane = tid & 31;
    const int jq8 = warp & 7;
    const int jgl = jq8 * 32 + lane;
    const int rh  = warp >> 3;

    // ---- K straight from global into registers
    float K0[16];
    {
        const float4* Kg = (const float4*)(g_K + (hbase + jgl) * 16);
#pragma unroll
        for (int qq = 0; qq < 4; qq++) *(float4*)(K0 + 4 * qq) = Kg[qq];
    }

    // ---- stage V (contiguous), Q (scaled), per-head table
    {
        const float4* Vg = (const float4*)(g_V + hbase * 16);
#pragma unroll
        for (int p = 0; p < 2; p++) {
            int q4 = tid + 512 * p;
            *(float4*)(sV + q4 * 4) = Vg[q4];
        }
        if (tid < 128) {
            float4 qv = *(const float4*)(g_Q + (hbase + itile) * 16 + tid * 4);
            qv.x *= NORMC; qv.y *= NORMC; qv.z *= NORMC; qv.w *= NORMC;
            *(float4*)(Qsm + tid * 4) = qv;
        }
        if (tid < 304) {
            sT[tid * 2]     = g_tab[tid * 16 + head * 2];
            sT[tid * 2 + 1] = g_tab[tid * 16 + head * 2 + 1];
        }
    }
    __syncthreads();

    // ---- P1: SP = bias(e) + Q.K   (bias fused; e/seg prefetched 1 row ahead)
    {
        const size_t gbase = (size_t)(b * NN + itile) * NN + jgl;
        const int rbase = rh * 16;

        float e_nxt = Ebm[gbase + (size_t)rbase * NN];
        unsigned short s_nxt = g_seg[gbase + (size_t)rbase * NN];

#pragma unroll 4
        for (int rr = 0; rr < 16; rr++) {
            const int r = rbase + rr;
            float e_cur = e_nxt;
            unsigned short s_cur = s_nxt;
            if (rr < 15) {
                e_nxt = Ebm[gbase + (size_t)(r + 1) * NN];
                s_nxt = g_seg[gbase + (size_t)(r + 1) * NN];
            }
            const float* qp = Qsm + r * 16;
            float4 q0 = *(const float4*)(qp);
            float4 q1 = *(const float4*)(qp + 4);
            float4 q2 = *(const float4*)(qp + 8);
            float4 q3 = *(const float4*)(qp + 12);
            float d = 0.f;
            d = fmaf(q0.x, K0[0], d);  d = fmaf(q0.y, K0[1], d);
            d = fmaf(q0.z, K0[2], d);  d = fmaf(q0.w, K0[3], d);
            d = fmaf(q1.x, K0[4], d);  d = fmaf(q1.y, K0[5], d);
            d = fmaf(q1.z, K0[6], d);  d = fmaf(q1.w, K0[7], d);
            d = fmaf(q2.x, K0[8], d);  d = fmaf(q2.y, K0[9], d);
            d = fmaf(q2.z, K0[10], d); d = fmaf(q2.w, K0[11], d);
            d = fmaf(q3.x, K0[12], d); d = fmaf(q3.y, K0[13], d);
            d = fmaf(q3.z, K0[14], d); d = fmaf(q3.w, K0[15], d);

            int seg = s_cur & 0x7fff;
            float2 t = *(const float2*)(sT + seg * 2);
            float bias = (s_cur & 0x8000) ? -INFINITY : fmaf(t.x, e_cur, t.y);
            SP[r * SPS + jgl] = bias + d;       // -inf + d = -inf
        }
    }
    __syncthreads();

    // ---- P2: softmax per row, in place (warp = 2 rows; conflict-free strided)
    {
#pragma unroll
        for (int rr = 0; rr < 2; rr++) {
            const int r = warp * 2 + rr;
            float v[8];
#pragma unroll
            for (int m = 0; m < 8; m++) v[m] = SP[r * SPS + lane + 32 * m];
            float mx = v[0];
#pragma unroll
            for (int m = 1; m < 8; m++) mx = fmaxf(mx, v[m]);
#pragma unroll
            for (int o = 16; o > 0; o >>= 1) mx = fmaxf(mx, __shfl_xor_sync(0xffffffffu, mx, o));
            float s = 0.f;
#pragma unroll
            for (int m = 0; m < 8; m++) { v[m] = __expf(v[m] - mx); s += v[m]; }
#pragma unroll
            for (int o = 16; o > 0; o >>= 1) s += __shfl_xor_sync(0xffffffffu, s, o);
            float inv = 1.f / s;
#pragma unroll
            for (int m = 0; m < 8; m++) SP[r * SPS + lane + 32 * m] = v[m] * inv;
        }
    }
    __syncthreads();

    // ---- P3: AV. warp = 16-j group; lane = row. conflict-free p loads.
    {
        const int j0 = warp * 16;
        float acc[16];
#pragma unroll
        for (int v = 0; v < 16; v++) acc[v] = 0.f;
#pragma unroll
        for (int jj = 0; jj < 16; jj++) {
            const int j = j0 + jj;
            float p = SP[lane * SPS + j];                      // (lane+j)%32 distinct
            const float4* vp = (const float4*)(sV + j * 16);   // broadcast
            float4 v0 = vp[0], v1 = vp[1], v2 = vp[2], v3 = vp[3];
            acc[0]  = fmaf(p, v0.x, acc[0]);  acc[1]  = fmaf(p, v0.y, acc[1]);
            acc[2]  = fmaf(p, v0.z, acc[2]);  acc[3]  = fmaf(p, v0.w, acc[3]);
            acc[4]  = fmaf(p, v1.x, acc[4]);  acc[5]  = fmaf(p, v1.y, acc[5]);
            acc[6]  = fmaf(p, v1.z, acc[6]);  acc[7]  = fmaf(p, v1.w, acc[7]);
            acc[8]  = fmaf(p, v2.x, acc[8]);  acc[9]  = fmaf(p, v2.y, acc[9]);
            acc[10] = fmaf(p, v2.z, acc[10]); acc[11] = fmaf(p, v2.w, acc[11]);
            acc[12] = fmaf(p, v3.x, acc[12]); acc[13] = fmaf(p, v3.y, acc[13]);
            acc[14] = fmaf(p, v3.z, acc[14]); acc[15] = fmaf(p, v3.w, acc[15]);
        }
        float* rp = red + (warp * 32 + lane) * RST;
#pragma unroll
        for (int v = 0; v < 16; v++) rp[v] = acc[v];           // stride 17, conflict-free
    }
    __syncthreads();

    // ---- P4: sum 16 j-group partials, write g_heads
    {
        const int r = tid >> 4, v = tid & 15;
        float s = 0.f;
#pragma unroll
        for (int jq = 0; jq < 16; jq++)
            s += red[(jq * 32 + r) * RST + v];
        g_heads[(size_t)(b * NN + itile + r) * HK + head * 16 + v] = s;
    }
}

// =====================================================================
// host launcher
// =====================================================================
extern "C" void kernel_launch(void* const* d_in, const int* in_sizes, int n_in,
                              void* d_out, int out_size)
{
    (void)in_sizes; (void)n_in; (void)out_size;
    const float* q    = (const float*)d_in[0];
    const float* hx   = (const float*)d_in[1];
    const int*   mask = (const int*)d_in[2];
    const float* edge = (const float*)d_in[3];
    const float* Wq   = (const float*)d_in[4];
    const float* Wk   = (const float*)d_in[5];
    const float* Wv   = (const float*)d_in[6];
    const float* Wo   = (const float*)d_in[7];
    const float* mw1  = (const float*)d_in[8];
    const float* mb1  = (const float*)d_in[9];
    const float* mw2  = (const float*)d_in[10];
    const float* mb2  = (const float*)d_in[11];
    const float* mw3  = (const float*)d_in[12];
    const float* mb3  = (const float*)d_in[13];

    const int smem_gemm = (128 * 128 + 64 * AS) * 4;
    const int smem_attn = 22144 * 4;   // 88,576 B

    cudaFuncSetAttribute(gemm_qkv_kernel,   cudaFuncAttributeMaxDynamicSharedMemorySize, smem_gemm);
    cudaFuncSetAttribute(gemm_out_kernel,   cudaFuncAttributeMaxDynamicSharedMemorySize, smem_gemm);
    cudaFuncSetAttribute(attn_fused_kernel, cudaFuncAttributeMaxDynamicSharedMemorySize, smem_attn);

    pwl_build_kernel<<<1, 512>>>(mw1, mb1, mw2, mb2, mw3, mb3);

    gemm_qkv_kernel<<<dim3(ROWS / 64, 3), 256, smem_gemm>>>(q, hx, Wq, Wk, Wv);

    seg_kernel<<<(BB * NN * NN) / (512 * 4), 512>>>(edge, mask);

    attn_fused_kernel<<<dim3(64, BB), 512, smem_attn>>>(edge);

    gemm_out_kernel<<<ROWS / 64, 256, smem_gemm>>>(Wo, (float*)d_out);
}

// round 11
// speedup vs baseline: 1.1237x; 1.0233x over previous
#include <cuda_runtime.h>
#include <math.h>
#include <stdint.h>

// Problem constants
#define BB   128
#define NN   256
#define DIN  128
#define HH   8
#define DK   16
#define HK   128
#define ROWS (BB*NN)        // 32768
#define NORMC 0.25f
#define AS   132            // GEMM A smem stride
#define SPS  257            // score/prob row stride (odd => conflict-free)
#define RST  18             // red row stride (even => 8B-aligned packed I/O)

typedef unsigned long long u64;

// ---- f32x2 packed math (sm_103a; ptxas never auto-fuses) ----
__device__ __forceinline__ u64 pack2(float a, float b) {
    u64 r; asm("mov.b64 %0, {%1, %2};" : "=l"(r) : "f"(a), "f"(b)); return r;
}
__device__ __forceinline__ u64 fma2(u64 a, u64 b, u64 c) {
    u64 d; asm("fma.rn.f32x2 %0, %1, %2, %3;" : "=l"(d) : "l"(a), "l"(b), "l"(c)); return d;
}
__device__ __forceinline__ u64 addp2(u64 a, u64 b) {
    u64 d; asm("add.rn.f32x2 %0, %1, %2;" : "=l"(d) : "l"(a), "l"(b)); return d;
}
__device__ __forceinline__ float2 unpack2(u64 v) {
    float2 f; asm("mov.b64 {%0, %1}, %2;" : "=f"(f.x), "=f"(f.y) : "l"(v)); return f;
}

// ---------------- device-global scratch ----------------
// Q/K/V head-major: [h][b*N+n][16]
__device__ float g_Q[(size_t)HH * ROWS * DK];
__device__ float g_K[(size_t)HH * ROWS * DK];
__device__ float g_V[(size_t)HH * ROWS * DK];
__device__ float g_heads[(size_t)ROWS * HK];

__device__ float g_breaks[512];
__device__ float g_tab[512 * 16];
__device__ unsigned short g_seg[(size_t)BB * NN * NN]; // seg | mask<<15

// =====================================================================
// PWL build (one block, 512 threads)
// =====================================================================
__global__ void pwl_build_kernel(const float* __restrict__ mw1, const float* __restrict__ mb1,
                                 const float* __restrict__ mw2, const float* __restrict__ mb2,
                                 const float* __restrict__ mw3, const float* __restrict__ mb3)
{
    __shared__ float w1[16], b1[16], w2[256], b2[16], w3[128], b3[8];
    __shared__ float tsort[16];
    __shared__ float cand[512];
    __shared__ int   cnt;

    const int tid = threadIdx.x;
    if (tid < 16)  { w1[tid] = mw1[tid]; b1[tid] = mb1[tid]; b2[tid] = mb2[tid]; }
    if (tid < 256) w2[tid] = mw2[tid];
    if (tid < 128) w3[tid] = mw3[tid];
    if (tid < 8)   b3[tid] = mb3[tid];
    cand[tid] = 3.0e38f;
    if (tid == 0) cnt = 16;
    __syncthreads();

    if (tid < 16) {
        float t = (w1[tid] != 0.f) ? (-b1[tid] / w1[tid]) : 3.0e38f;
        cand[tid] = t;
    }
    __syncthreads();
    if (tid == 0) {
        for (int i = 0; i < 16; i++) tsort[i] = cand[i];
        for (int i = 1; i < 16; i++) {
            float v = tsort[i]; int k = i - 1;
            while (k >= 0 && tsort[k] > v) { tsort[k + 1] = tsort[k]; k--; }
            tsort[k + 1] = v;
        }
    }
    __syncthreads();

    if (tid < 17 * 16) {
        int iv = tid >> 4, c = tid & 15;
        float lo = (iv == 0)  ? -3.0e38f : tsort[iv - 1];
        float hi = (iv == 16) ?  3.0e38f : tsort[iv];
        if (lo < hi) {
            float m;
            if (lo <= -1e30f && hi >= 1e30f) m = 0.f;
            else if (lo <= -1e30f)           m = hi - 1.f;
            else if (hi >=  1e30f)           m = lo + 1.f;
            else                             m = 0.5f * (lo + hi);
            float g = 0.f, q = b2[c];
            for (int n = 0; n < 16; n++) {
                if (fmaf(m, w1[n], b1[n]) > 0.f) {
                    g = fmaf(w1[n], w2[n * 16 + c], g);
                    q = fmaf(b1[n], w2[n * 16 + c], q);
                }
            }
            if (g != 0.f) {
                float x = -q / g;
                if (x > lo && x < hi && fabsf(x) < 1e30f) {
                    int k = atomicAdd(&cnt, 1);
                    cand[k] = x;
                }
            }
        }
    }
    __syncthreads();
    const int ncand = cnt;

    for (int k = 2; k <= 512; k <<= 1) {
        for (int j = k >> 1; j > 0; j >>= 1) {
            int ixj = tid ^ j;
            if (ixj > tid) {
                bool up = (tid & k) == 0;
                float a = cand[tid], b = cand[ixj];
                if ((a > b) == up) { cand[tid] = b; cand[ixj] = a; }
            }
            __syncthreads();
        }
    }

    g_breaks[tid] = (tid < ncand) ? cand[tid] : 3.0e38f;

    if (tid <= ncand) {
        float lo = (tid == 0)     ? -3.0e38f : cand[tid - 1];
        float hi = (tid == ncand) ?  3.0e38f : cand[tid];
        float m;
        if (lo <= -1e30f && hi >= 1e30f) m = 0.f;
        else if (lo <= -1e30f)           m = hi - 1.f;
        else if (hi >=  1e30f)           m = lo + 1.f;
        else                             m = 0.5f * (lo + hi);

        float slope[8], inter[8];
        for (int h = 0; h < 8; h++) { slope[h] = 0.f; inter[h] = b3[h]; }
        for (int c = 0; c < 16; c++) {
            float gc = 0.f, qc = b2[c];
            for (int n = 0; n < 16; n++) {
                if (fmaf(m, w1[n], b1[n]) > 0.f) {
                    gc = fmaf(w1[n], w2[n * 16 + c], gc);
                    qc = fmaf(b1[n], w2[n * 16 + c], qc);
                }
            }
            if (fmaf(gc, m, qc) > 0.f) {
                for (int h = 0; h < 8; h++) {
                    slope[h] = fmaf(gc, w3[c * 8 + h], slope[h]);
                    inter[h] = fmaf(qc, w3[c * 8 + h], inter[h]);
                }
            }
        }
        for (int h = 0; h < 8; h++) {
            g_tab[tid * 16 + h * 2]     = slope[h];
            g_tab[tid * 16 + h * 2 + 1] = inter[h];
        }
    }
}

// =====================================================================
// seg kernel: per (b,i,j) binary-search segment; fold mask into bit 15
// =====================================================================
__global__ void __launch_bounds__(512) seg_kernel(const float* __restrict__ Ebm,
                                                  const int* __restrict__ mask)
{
    __shared__ float sB[512];
    const int tid = threadIdx.x;
    sB[tid] = g_breaks[tid];
    __syncthreads();

    const size_t v = (size_t)blockIdx.x * 512 + tid;
    float4 e4 = ((const float4*)Ebm)[v];
    int4   m4 = ((const int4*)mask)[v];
    ushort4 out;
    const float ev[4] = {e4.x, e4.y, e4.z, e4.w};
    const int   mv[4] = {m4.x, m4.y, m4.z, m4.w};
    unsigned short ov[4];
#pragma unroll
    for (int p = 0; p < 4; p++) {
        float e = ev[p];
        int seg = 0;
#pragma unroll
        for (int st = 256; st >= 1; st >>= 1) {
            int cnd = seg + st;
            if (e >= sB[cnd - 1]) seg = cnd;
        }
        ov[p] = (unsigned short)(seg | (mv[p] ? 0x8000 : 0));
    }
    out.x = ov[0]; out.y = ov[1]; out.z = ov[2]; out.w = ov[3];
    ((ushort4*)g_seg)[v] = out;
}

// =====================================================================
// GEMM body, f32x2 inner loop.
// =====================================================================
__device__ __forceinline__ void gemm_body(const float* __restrict__ A,
                                          const float* __restrict__ Wraw,
                                          float* __restrict__ Out,
                                          int mode, int row0)
{
    extern __shared__ float sm[];
    float* Wsm = sm;
    float* Asm = sm + 128 * 128;

    const int tid = threadIdx.x;

    for (int i4 = tid; i4 < 4096; i4 += 256) {
        int d = i4 >> 5, c4 = (i4 & 31) * 4;
        float4 w;
        if (mode == 0) w = *(const float4*)(Wraw + (c4 >> 4) * (DIN * 16) + d * 16 + (c4 & 15));
        else           w = *(const float4*)(Wraw + d * 128 + c4);
        *(float4*)(Wsm + d * 128 + c4) = w;
    }
    for (int i4 = tid; i4 < 2048; i4 += 256) {
        int r = i4 >> 5, c4 = (i4 & 31) * 4;
        *(float4*)(Asm + r * AS + c4) = *(const float4*)(A + (size_t)(row0 + r) * 128 + c4);
    }
    __syncthreads();

    const int tx = tid & 15, ty = tid >> 4;
    const int ca = tx * 4;
    const int r0 = ty * 4;
    u64 acc2[4][4];
#pragma unroll
    for (int u = 0; u < 4; u++)
#pragma unroll
        for (int k = 0; k < 4; k++) acc2[u][k] = 0ull;

#pragma unroll 2
    for (int dc = 0; dc < 128; dc += 4) {
        float4 a4[4];
#pragma unroll
        for (int u = 0; u < 4; u++) a4[u] = *(const float4*)(Asm + (r0 + u) * AS + dc);
#pragma unroll
        for (int dd = 0; dd < 4; dd++) {
            ulonglong2 w0 = *(const ulonglong2*)(Wsm + (dc + dd) * 128 + ca);
            ulonglong2 w1 = *(const ulonglong2*)(Wsm + (dc + dd) * 128 + 64 + ca);
#pragma unroll
            for (int u = 0; u < 4; u++) {
                float a = (dd == 0) ? a4[u].x : (dd == 1) ? a4[u].y : (dd == 2) ? a4[u].z : a4[u].w;
                u64 a2 = pack2(a, a);
                acc2[u][0] = fma2(a2, w0.x, acc2[u][0]);
                acc2[u][1] = fma2(a2, w0.y, acc2[u][1]);
                acc2[u][2] = fma2(a2, w1.x, acc2[u][2]);
                acc2[u][3] = fma2(a2, w1.y, acc2[u][3]);
            }
        }
    }
#pragma unroll
    for (int u = 0; u < 4; u++) {
        float2 p0 = unpack2(acc2[u][0]), p1 = unpack2(acc2[u][1]);
        float2 p2 = unpack2(acc2[u][2]), p3 = unpack2(acc2[u][3]);
        float4 o0 = {p0.x, p0.y, p1.x, p1.y};
        float4 o1 = {p2.x, p2.y, p3.x, p3.y};
        const int row = row0 + r0 + u;
        if (mode == 0) {
            int h0 = ca >> 4, h1 = (64 + ca) >> 4;
            *(float4*)(Out + ((size_t)h0 * ROWS + row) * 16 + (ca & 15)) = o0;
            *(float4*)(Out + ((size_t)h1 * ROWS + row) * 16 + (ca & 15)) = o1;
        } else {
            float* orow = Out + (size_t)row * 128;
            *(float4*)(orow + ca)      = o0;
            *(float4*)(orow + 64 + ca) = o1;
        }
    }
}

__global__ void __launch_bounds__(256) gemm_qkv_kernel(const float* __restrict__ q,
                                                       const float* __restrict__ hx,
                                                       const float* __restrict__ Wq,
                                                       const float* __restrict__ Wk,
                                                       const float* __restrict__ Wv)
{
    const int z = blockIdx.y;
    const float* A = (z == 0) ? q : hx;
    const float* W = (z == 0) ? Wq : (z == 1) ? Wk : Wv;
    float* Out = (z == 0) ? g_Q : (z == 1) ? g_K : g_V;
    gemm_body(A, W, Out, 0, blockIdx.x * 64);
}

__global__ void __launch_bounds__(256) gemm_out_kernel(const float* __restrict__ Wo,
                                                       float* __restrict__ Out)
{
    gemm_body(g_heads, Wo, Out, 1, blockIdx.x * 64);
}

// =====================================================================
// Fused attention v7: v6 + f32x2 in P3/P4.
// Block = (b, 32-row tile, head). 512 threads, 2 blocks/SM.
// smem (floats): SP 32x257=8224 | red 16x32x18=9216 | V 4096 | Q 512
//                | sT 608  total 22656 f = 90,624 B
// =====================================================================
__global__ void __launch_bounds__(512, 2)
attn_fused_kernel(const float* __restrict__ Ebm)
{
    extern __shared__ float sm[];
    float* SP  = sm;                 // [32][257] scores -> probs (in place)
    float* red = SP + 8224;          // [16][32][18]
    float* sV  = red + 9216;         // [256][16]
    float* Qsm = sV + 4096;          // [32][16] (pre-scaled by NORMC)
    float* sT  = Qsm + 512;          // [304][2] slope/inter for this head

    const int tid   = threadIdx.x;
    const int b     = blockIdx.y;
    const int itile = (blockIdx.x & 7) * 32;
    const int head  = blockIdx.x >> 3;

    const size_t hbase = (size_t)head * ROWS + (size_t)b * NN;

    const int warp = tid >> 5, lane = tid & 31;
    const int jq8 = warp & 7;
    const int jgl = jq8 * 32 + lane;
    const int rh  = warp >> 3;

    // ---- K straight from global into registers
    float K0[16];
    {
        const float4* Kg = (const float4*)(g_K + (hbase + jgl) * 16);
#pragma unroll
        for (int qq = 0; qq < 4; qq++) *(float4*)(K0 + 4 * qq) = Kg[qq];
    }

    // ---- stage V (contiguous), Q (scaled), per-head table
    {
        const float4* Vg = (const float4*)(g_V + hbase * 16);
#pragma unroll
        for (int p = 0; p < 2; p++) {
            int q4 = tid + 512 * p;
            *(float4*)(sV + q4 * 4) = Vg[q4];
        }
        if (tid < 128) {
            float4 qv = *(const float4*)(g_Q + (hbase + itile) * 16 + tid * 4);
            qv.x *= NORMC; qv.y *= NORMC; qv.z *= NORMC; qv.w *= NORMC;
            *(float4*)(Qsm + tid * 4) = qv;
        }
        if (tid < 304) {
            sT[tid * 2]     = g_tab[tid * 16 + head * 2];
            sT[tid * 2 + 1] = g_tab[tid * 16 + head * 2 + 1];
        }
    }
    __syncthreads();

    // ---- P1: SP = bias(e) + Q.K   (bias fused; e/seg prefetched 1 row ahead)
    {
        const size_t gbase = (size_t)(b * NN + itile) * NN + jgl;
        const int rbase = rh * 16;

        float e_nxt = Ebm[gbase + (size_t)rbase * NN];
        unsigned short s_nxt = g_seg[gbase + (size_t)rbase * NN];

#pragma unroll 4
        for (int rr = 0; rr < 16; rr++) {
            const int r = rbase + rr;
            float e_cur = e_nxt;
            unsigned short s_cur = s_nxt;
            if (rr < 15) {
                e_nxt = Ebm[gbase + (size_t)(r + 1) * NN];
                s_nxt = g_seg[gbase + (size_t)(r + 1) * NN];
            }
            const float* qp = Qsm + r * 16;
            float4 q0 = *(const float4*)(qp);
            float4 q1 = *(const float4*)(qp + 4);
            float4 q2 = *(const float4*)(qp + 8);
            float4 q3 = *(const float4*)(qp + 12);
            float d = 0.f;
            d = fmaf(q0.x, K0[0], d);  d = fmaf(q0.y, K0[1], d);
            d = fmaf(q0.z, K0[2], d);  d = fmaf(q0.w, K0[3], d);
            d = fmaf(q1.x, K0[4], d);  d = fmaf(q1.y, K0[5], d);
            d = fmaf(q1.z, K0[6], d);  d = fmaf(q1.w, K0[7], d);
            d = fmaf(q2.x, K0[8], d);  d = fmaf(q2.y, K0[9], d);
            d = fmaf(q2.z, K0[10], d); d = fmaf(q2.w, K0[11], d);
            d = fmaf(q3.x, K0[12], d); d = fmaf(q3.y, K0[13], d);
            d = fmaf(q3.z, K0[14], d); d = fmaf(q3.w, K0[15], d);

            int seg = s_cur & 0x7fff;
            float2 t = *(const float2*)(sT + seg * 2);
            float bias = (s_cur & 0x8000) ? -INFINITY : fmaf(t.x, e_cur, t.y);
            SP[r * SPS + jgl] = bias + d;       // -inf + d = -inf
        }
    }
    __syncthreads();

    // ---- P2: softmax per row, in place (warp = 2 rows; conflict-free strided)
    {
#pragma unroll
        for (int rr = 0; rr < 2; rr++) {
            const int r = warp * 2 + rr;
            float v[8];
#pragma unroll
            for (int m = 0; m < 8; m++) v[m] = SP[r * SPS + lane + 32 * m];
            float mx = v[0];
#pragma unroll
            for (int m = 1; m < 8; m++) mx = fmaxf(mx, v[m]);
#pragma unroll
            for (int o = 16; o > 0; o >>= 1) mx = fmaxf(mx, __shfl_xor_sync(0xffffffffu, mx, o));
            float s = 0.f;
#pragma unroll
            for (int m = 0; m < 8; m++) { v[m] = __expf(v[m] - mx); s += v[m]; }
#pragma unroll
            for (int o = 16; o > 0; o >>= 1) s += __shfl_xor_sync(0xffffffffu, s, o);
            float inv = 1.f / s;
#pragma unroll
            for (int m = 0; m < 8; m++) SP[r * SPS + lane + 32 * m] = v[m] * inv;
        }
    }
    __syncthreads();

    // ---- P3: AV with f32x2 packed acc. warp = 16-j group; lane = row.
    {
        const int j0 = warp * 16;
        u64 acc[8];
#pragma unroll
        for (int v = 0; v < 8; v++) acc[v] = 0ull;
#pragma unroll
        for (int jj = 0; jj < 16; jj++) {
            const int j = j0 + jj;
            float p = SP[lane * SPS + j];                      // conflict-free
            u64 p2 = pack2(p, p);
            const ulonglong2* vp = (const ulonglong2*)(sV + j * 16);  // broadcast
            ulonglong2 va = vp[0], vb = vp[1];
            acc[0] = fma2(p2, va.x, acc[0]); acc[1] = fma2(p2, va.y, acc[1]);
            acc[2] = fma2(p2, vb.x, acc[2]); acc[3] = fma2(p2, vb.y, acc[3]);
            ulonglong2 vc = vp[2], vd = vp[3];
            acc[4] = fma2(p2, vc.x, acc[4]); acc[5] = fma2(p2, vc.y, acc[5]);
            acc[6] = fma2(p2, vd.x, acc[6]); acc[7] = fma2(p2, vd.y, acc[7]);
        }
        u64* rp = (u64*)(red + (warp * 32 + lane) * RST);      // 8B-aligned (RST even)
#pragma unroll
        for (int v = 0; v < 8; v++) rp[v] = acc[v];
    }
    __syncthreads();

    // ---- P4: sum 16 j-group partials (packed), write g_heads
    if (tid < 256) {
        const int r = tid >> 3, vp = tid & 7;
        u64 s = 0ull;
#pragma unroll
        for (int jq = 0; jq < 16; jq++)
            s = addp2(s, *(const u64*)(red + (jq * 32 + r) * RST + vp * 2));
        float2 f = unpack2(s);
        *(float2*)(g_heads + (size_t)(b * NN + itile + r) * HK + head * 16 + vp * 2) = f;
    }
}

// =====================================================================
// host launcher
// =====================================================================
extern "C" void kernel_launch(void* const* d_in, const int* in_sizes, int n_in,
                              void* d_out, int out_size)
{
    (void)in_sizes; (void)n_in; (void)out_size;
    const float* q    = (const float*)d_in[0];
    const float* hx   = (const float*)d_in[1];
    const int*   mask = (const int*)d_in[2];
    const float* edge = (const float*)d_in[3];
    const float* Wq   = (const float*)d_in[4];
    const float* Wk   = (const float*)d_in[5];
    const float* Wv   = (const float*)d_in[6];
    const float* Wo   = (const float*)d_in[7];
    const float* mw1  = (const float*)d_in[8];
    const float* mb1  = (const float*)d_in[9];
    const float* mw2  = (const float*)d_in[10];
    const float* mb2  = (const float*)d_in[11];
    const float* mw3  = (const float*)d_in[12];
    const float* mb3  = (const float*)d_in[13];

    const int smem_gemm = (128 * 128 + 64 * AS) * 4;
    const int smem_attn = 22656 * 4;   // 90,624 B

    cudaFuncSetAttribute(gemm_qkv_kernel,   cudaFuncAttributeMaxDynamicSharedMemorySize, smem_gemm);
    cudaFuncSetAttribute(gemm_out_kernel,   cudaFuncAttributeMaxDynamicSharedMemorySize, smem_gemm);
    cudaFuncSetAttribute(attn_fused_kernel, cudaFuncAttributeMaxDynamicSharedMemorySize, smem_attn);

    pwl_build_kernel<<<1, 512>>>(mw1, mb1, mw2, mb2, mw3, mb3);

    gemm_qkv_kernel<<<dim3(ROWS / 64, 3), 256, smem_gemm>>>(q, hx, Wq, Wk, Wv);

    seg_kernel<<<(BB * NN * NN) / (512 * 4), 512>>>(edge, mask);

    attn_fused_kernel<<<dim3(64, BB), 512, smem_attn>>>(edge);

    gemm_out_kernel<<<ROWS / 64, 256, smem_gemm>>>(Wo, (float*)d_out);
}

// round 13
// speedup vs baseline: 1.2132x; 1.0796x over previous
#include <cuda_runtime.h>
#include <math.h>
#include <stdint.h>

// Problem constants
#define BB   128
#define NN   256
#define DIN  128
#define HH   8
#define DK   16
#define HK   128
#define ROWS (BB*NN)        // 32768
#define NORMC 0.25f
#define AS   132            // GEMM A smem stride
#define SPS  257            // score/prob row stride (odd => conflict-free)
#define RST  20             // red row stride (multiple of 4 => 16B-aligned rows)

typedef unsigned long long u64;

// ---- f32x2 packed math ----
__device__ __forceinline__ u64 pack2(float a, float b) {
    u64 r; asm("mov.b64 %0, {%1, %2};" : "=l"(r) : "f"(a), "f"(b)); return r;
}
__device__ __forceinline__ u64 fma2(u64 a, u64 b, u64 c) {
    u64 d; asm("fma.rn.f32x2 %0, %1, %2, %3;" : "=l"(d) : "l"(a), "l"(b), "l"(c)); return d;
}
__device__ __forceinline__ u64 addp2(u64 a, u64 b) {
    u64 d; asm("add.rn.f32x2 %0, %1, %2;" : "=l"(d) : "l"(a), "l"(b)); return d;
}
__device__ __forceinline__ float2 unpack2(u64 v) {
    float2 f; asm("mov.b64 {%0, %1}, %2;" : "=f"(f.x), "=f"(f.y) : "l"(v)); return f;
}

// ---------------- device-global scratch ----------------
// Q/K/V head-major: [h][b*N+n][16]
__device__ float g_Q[(size_t)HH * ROWS * DK];
__device__ float g_K[(size_t)HH * ROWS * DK];
__device__ float g_V[(size_t)HH * ROWS * DK];
__device__ float g_heads[(size_t)ROWS * HK];

__device__ float g_breaks[512];
__device__ float g_tab[512 * 16];
__device__ unsigned short g_seg[(size_t)BB * NN * NN]; // seg | mask<<15

// =====================================================================
// PWL build (one block, 512 threads)
// =====================================================================
__global__ void pwl_build_kernel(const float* __restrict__ mw1, const float* __restrict__ mb1,
                                 const float* __restrict__ mw2, const float* __restrict__ mb2,
                                 const float* __restrict__ mw3, const float* __restrict__ mb3)
{
    __shared__ float w1[16], b1[16], w2[256], b2[16], w3[128], b3[8];
    __shared__ float tsort[16];
    __shared__ float cand[512];
    __shared__ int   cnt;

    const int tid = threadIdx.x;
    if (tid < 16)  { w1[tid] = mw1[tid]; b1[tid] = mb1[tid]; b2[tid] = mb2[tid]; }
    if (tid < 256) w2[tid] = mw2[tid];
    if (tid < 128) w3[tid] = mw3[tid];
    if (tid < 8)   b3[tid] = mb3[tid];
    cand[tid] = 3.0e38f;
    if (tid == 0) cnt = 16;
    __syncthreads();

    if (tid < 16) {
        float t = (w1[tid] != 0.f) ? (-b1[tid] / w1[tid]) : 3.0e38f;
        cand[tid] = t;
    }
    __syncthreads();
    if (tid == 0) {
        for (int i = 0; i < 16; i++) tsort[i] = cand[i];
        for (int i = 1; i < 16; i++) {
            float v = tsort[i]; int k = i - 1;
            while (k >= 0 && tsort[k] > v) { tsort[k + 1] = tsort[k]; k--; }
            tsort[k + 1] = v;
        }
    }
    __syncthreads();

    if (tid < 17 * 16) {
        int iv = tid >> 4, c = tid & 15;
        float lo = (iv == 0)  ? -3.0e38f : tsort[iv - 1];
        float hi = (iv == 16) ?  3.0e38f : tsort[iv];
        if (lo < hi) {
            float m;
            if (lo <= -1e30f && hi >= 1e30f) m = 0.f;
            else if (lo <= -1e30f)           m = hi - 1.f;
            else if (hi >=  1e30f)           m = lo + 1.f;
            else                             m = 0.5f * (lo + hi);
            float g = 0.f, q = b2[c];
            for (int n = 0; n < 16; n++) {
                if (fmaf(m, w1[n], b1[n]) > 0.f) {
                    g = fmaf(w1[n], w2[n * 16 + c], g);
                    q = fmaf(b1[n], w2[n * 16 + c], q);
                }
            }
            if (g != 0.f) {
                float x = -q / g;
                if (x > lo && x < hi && fabsf(x) < 1e30f) {
                    int k = atomicAdd(&cnt, 1);
                    cand[k] = x;
                }
            }
        }
    }
    __syncthreads();
    const int ncand = cnt;

    for (int k = 2; k <= 512; k <<= 1) {
        for (int j = k >> 1; j > 0; j >>= 1) {
            int ixj = tid ^ j;
            if (ixj > tid) {
                bool up = (tid & k) == 0;
                float a = cand[tid], b = cand[ixj];
                if ((a > b) == up) { cand[tid] = b; cand[ixj] = a; }
            }
            __syncthreads();
        }
    }

    g_breaks[tid] = (tid < ncand) ? cand[tid] : 3.0e38f;

    if (tid <= ncand) {
        float lo = (tid == 0)     ? -3.0e38f : cand[tid - 1];
        float hi = (tid == ncand) ?  3.0e38f : cand[tid];
        float m;
        if (lo <= -1e30f && hi >= 1e30f) m = 0.f;
        else if (lo <= -1e30f)           m = hi - 1.f;
        else if (hi >=  1e30f)           m = lo + 1.f;
        else                             m = 0.5f * (lo + hi);

        float slope[8], inter[8];
        for (int h = 0; h < 8; h++) { slope[h] = 0.f; inter[h] = b3[h]; }
        for (int c = 0; c < 16; c++) {
            float gc = 0.f, qc = b2[c];
            for (int n = 0; n < 16; n++) {
                if (fmaf(m, w1[n], b1[n]) > 0.f) {
                    gc = fmaf(w1[n], w2[n * 16 + c], gc);
                    qc = fmaf(b1[n], w2[n * 16 + c], qc);
                }
            }
            if (fmaf(gc, m, qc) > 0.f) {
                for (int h = 0; h < 8; h++) {
                    slope[h] = fmaf(gc, w3[c * 8 + h], slope[h]);
                    inter[h] = fmaf(qc, w3[c * 8 + h], inter[h]);
                }
            }
        }
        for (int h = 0; h < 8; h++) {
            g_tab[tid * 16 + h * 2]     = slope[h];
            g_tab[tid * 16 + h * 2 + 1] = inter[h];
        }
    }
}

// =====================================================================
// seg kernel
// =====================================================================
__global__ void __launch_bounds__(512) seg_kernel(const float* __restrict__ Ebm,
                                                  const int* __restrict__ mask)
{
    __shared__ float sB[512];
    const int tid = threadIdx.x;
    sB[tid] = g_breaks[tid];
    __syncthreads();

    const size_t v = (size_t)blockIdx.x * 512 + tid;
    float4 e4 = ((const float4*)Ebm)[v];
    int4   m4 = ((const int4*)mask)[v];
    ushort4 out;
    const float ev[4] = {e4.x, e4.y, e4.z, e4.w};
    const int   mv[4] = {m4.x, m4.y, m4.z, m4.w};
    unsigned short ov[4];
#pragma unroll
    for (int p = 0; p < 4; p++) {
        float e = ev[p];
        int seg = 0;
#pragma unroll
        for (int st = 256; st >= 1; st >>= 1) {
            int cnd = seg + st;
            if (e >= sB[cnd - 1]) seg = cnd;
        }
        ov[p] = (unsigned short)(seg | (mv[p] ? 0x8000 : 0));
    }
    out.x = ov[0]; out.y = ov[1]; out.z = ov[2]; out.w = ov[3];
    ((ushort4*)g_seg)[v] = out;
}

// =====================================================================
// GEMM body, f32x2 inner loop (as R11)
// =====================================================================
__device__ __forceinline__ void gemm_body(const float* __restrict__ A,
                                          const float* __restrict__ Wraw,
                                          float* __restrict__ Out,
                                          int mode, int row0)
{
    extern __shared__ float sm[];
    float* Wsm = sm;
    float* Asm = sm + 128 * 128;

    const int tid = threadIdx.x;

    for (int i4 = tid; i4 < 4096; i4 += 256) {
        int d = i4 >> 5, c4 = (i4 & 31) * 4;
        float4 w;
        if (mode == 0) w = *(const float4*)(Wraw + (c4 >> 4) * (DIN * 16) + d * 16 + (c4 & 15));
        else           w = *(const float4*)(Wraw + d * 128 + c4);
        *(float4*)(Wsm + d * 128 + c4) = w;
    }
    for (int i4 = tid; i4 < 2048; i4 += 256) {
        int r = i4 >> 5, c4 = (i4 & 31) * 4;
        *(float4*)(Asm + r * AS + c4) = *(const float4*)(A + (size_t)(row0 + r) * 128 + c4);
    }
    __syncthreads();

    const int tx = tid & 15, ty = tid >> 4;
    const int ca = tx * 4;
    const int r0 = ty * 4;
    u64 acc2[4][4];
#pragma unroll
    for (int u = 0; u < 4; u++)
#pragma unroll
        for (int k = 0; k < 4; k++) acc2[u][k] = 0ull;

#pragma unroll 2
    for (int dc = 0; dc < 128; dc += 4) {
        float4 a4[4];
#pragma unroll
        for (int u = 0; u < 4; u++) a4[u] = *(const float4*)(Asm + (r0 + u) * AS + dc);
#pragma unroll
        for (int dd = 0; dd < 4; dd++) {
            ulonglong2 w0 = *(const ulonglong2*)(Wsm + (dc + dd) * 128 + ca);
            ulonglong2 w1 = *(const ulonglong2*)(Wsm + (dc + dd) * 128 + 64 + ca);
#pragma unroll
            for (int u = 0; u < 4; u++) {
                float a = (dd == 0) ? a4[u].x : (dd == 1) ? a4[u].y : (dd == 2) ? a4[u].z : a4[u].w;
                u64 a2 = pack2(a, a);
                acc2[u][0] = fma2(a2, w0.x, acc2[u][0]);
                acc2[u][1] = fma2(a2, w0.y, acc2[u][1]);
                acc2[u][2] = fma2(a2, w1.x, acc2[u][2]);
                acc2[u][3] = fma2(a2, w1.y, acc2[u][3]);
            }
        }
    }
#pragma unroll
    for (int u = 0; u < 4; u++) {
        float2 p0 = unpack2(acc2[u][0]), p1 = unpack2(acc2[u][1]);
        float2 p2 = unpack2(acc2[u][2]), p3 = unpack2(acc2[u][3]);
        float4 o0 = {p0.x, p0.y, p1.x, p1.y};
        float4 o1 = {p2.x, p2.y, p3.x, p3.y};
        const int row = row0 + r0 + u;
        if (mode == 0) {
            int h0 = ca >> 4, h1 = (64 + ca) >> 4;
            *(float4*)(Out + ((size_t)h0 * ROWS + row) * 16 + (ca & 15)) = o0;
            *(float4*)(Out + ((size_t)h1 * ROWS + row) * 16 + (ca & 15)) = o1;
        } else {
            float* orow = Out + (size_t)row * 128;
            *(float4*)(orow + ca)      = o0;
            *(float4*)(orow + 64 + ca) = o1;
        }
    }
}

__global__ void __launch_bounds__(256) gemm_qkv_kernel(const float* __restrict__ q,
                                                       const float* __restrict__ hx,
                                                       const float* __restrict__ Wq,
                                                       const float* __restrict__ Wk,
                                                       const float* __restrict__ Wv)
{
    const int z = blockIdx.y;
    const float* A = (z == 0) ? q : hx;
    const float* W = (z == 0) ? Wq : (z == 1) ? Wk : Wv;
    float* Out = (z == 0) ? g_Q : (z == 1) ? g_K : g_V;
    gemm_body(A, W, Out, 0, blockIdx.x * 64);
}

__global__ void __launch_bounds__(256) gemm_out_kernel(const float* __restrict__ Wo,
                                                       float* __restrict__ Out)
{
    gemm_body(g_heads, Wo, Out, 1, blockIdx.x * 64);
}

// =====================================================================
// Fused attention v8b: 2 i-tiles per block; P3 (2-row, 8-v) lanes; RST=20.
// Block = (b, 64-row region, head). 512 threads, 2 blocks/SM.
// smem (floats): SP 32x257=8224 | red 16x32x20=10240 | V 4096 | Q 512
//                | sT 608  total 23680 f = 94,720 B
// =====================================================================
__global__ void __launch_bounds__(512, 2)
attn_fused_kernel(const float* __restrict__ Ebm)
{
    extern __shared__ float sm[];
    float* SP  = sm;                 // [32][257] scores -> probs (in place)
    float* red = SP + 8224;          // [16][32][20]
    float* sV  = red + 10240;        // [256][16]
    float* Qsm = sV + 4096;          // [32][16] (pre-scaled by NORMC)
    float* sT  = Qsm + 512;          // [304][2] slope/inter for this head

    const int tid    = threadIdx.x;
    const int b      = blockIdx.y;
    const int itile0 = (blockIdx.x & 3) * 64;   // 64-row region
    const int head   = blockIdx.x >> 2;

    const size_t hbase = (size_t)head * ROWS + (size_t)b * NN;

    const int warp = tid >> 5, lane = tid & 31;
    const int jq8 = warp & 7;
    const int jgl = jq8 * 32 + lane;
    const int rh  = warp >> 3;

    // ---- K straight from global into registers (reused across both tiles)
    float K0[16];
    {
        const float4* Kg = (const float4*)(g_K + (hbase + jgl) * 16);
#pragma unroll
        for (int qq = 0; qq < 4; qq++) *(float4*)(K0 + 4 * qq) = Kg[qq];
    }

    // ---- stage V (contiguous), per-head table (once per block)
    {
        const float4* Vg = (const float4*)(g_V + hbase * 16);
#pragma unroll
        for (int p = 0; p < 2; p++) {
            int q4 = tid + 512 * p;
            *(float4*)(sV + q4 * 4) = Vg[q4];
        }
        if (tid < 304) {
            sT[tid * 2]     = g_tab[tid * 16 + head * 2];
            sT[tid * 2 + 1] = g_tab[tid * 16 + head * 2 + 1];
        }
    }

    for (int tile = 0; tile < 2; tile++) {
        const int itile = itile0 + tile * 32;

        // ---- stage Q (scaled) for this tile
        __syncthreads();   // (first iter: covers V/sT staging; later: red reads done)
        if (tid < 128) {
            float4 qv = *(const float4*)(g_Q + (hbase + itile) * 16 + tid * 4);
            qv.x *= NORMC; qv.y *= NORMC; qv.z *= NORMC; qv.w *= NORMC;
            *(float4*)(Qsm + tid * 4) = qv;
        }
        __syncthreads();

        // ---- P1: SP = bias(e) + Q.K  (bias fused; e/seg prefetched 1 row ahead)
        {
            const size_t gbase = (size_t)(b * NN + itile) * NN + jgl;
            const int rbase = rh * 16;

            float e_nxt = Ebm[gbase + (size_t)rbase * NN];
            unsigned short s_nxt = g_seg[gbase + (size_t)rbase * NN];

#pragma unroll 4
            for (int rr = 0; rr < 16; rr++) {
                const int r = rbase + rr;
                float e_cur = e_nxt;
                unsigned short s_cur = s_nxt;
                if (rr < 15) {
                    e_nxt = Ebm[gbase + (size_t)(r + 1) * NN];
                    s_nxt = g_seg[gbase + (size_t)(r + 1) * NN];
                }
                const float* qp = Qsm + r * 16;
                float4 q0 = *(const float4*)(qp);
                float4 q1 = *(const float4*)(qp + 4);
                float4 q2 = *(const float4*)(qp + 8);
                float4 q3 = *(const float4*)(qp + 12);
                float d = 0.f;
                d = fmaf(q0.x, K0[0], d);  d = fmaf(q0.y, K0[1], d);
                d = fmaf(q0.z, K0[2], d);  d = fmaf(q0.w, K0[3], d);
                d = fmaf(q1.x, K0[4], d);  d = fmaf(q1.y, K0[5], d);
                d = fmaf(q1.z, K0[6], d);  d = fmaf(q1.w, K0[7], d);
                d = fmaf(q2.x, K0[8], d);  d = fmaf(q2.y, K0[9], d);
                d = fmaf(q2.z, K0[10], d); d = fmaf(q2.w, K0[11], d);
                d = fmaf(q3.x, K0[12], d); d = fmaf(q3.y, K0[13], d);
                d = fmaf(q3.z, K0[14], d); d = fmaf(q3.w, K0[15], d);

                int seg = s_cur & 0x7fff;
                float2 t = *(const float2*)(sT + seg * 2);
                float bias = (s_cur & 0x8000) ? -INFINITY : fmaf(t.x, e_cur, t.y);
                SP[r * SPS + jgl] = bias + d;       // -inf + d = -inf
            }
        }
        __syncthreads();

        // ---- P2: softmax per row, in place (warp = 2 rows; conflict-free strided)
        {
#pragma unroll
            for (int rr = 0; rr < 2; rr++) {
                const int r = warp * 2 + rr;
                float v[8];
#pragma unroll
                for (int m = 0; m < 8; m++) v[m] = SP[r * SPS + lane + 32 * m];
                float mx = v[0];
#pragma unroll
                for (int m = 1; m < 8; m++) mx = fmaxf(mx, v[m]);
#pragma unroll
                for (int o = 16; o > 0; o >>= 1) mx = fmaxf(mx, __shfl_xor_sync(0xffffffffu, mx, o));
                float s = 0.f;
#pragma unroll
                for (int m = 0; m < 8; m++) { v[m] = __expf(v[m] - mx); s += v[m]; }
#pragma unroll
                for (int o = 16; o > 0; o >>= 1) s += __shfl_xor_sync(0xffffffffu, s, o);
                float inv = 1.f / s;
#pragma unroll
                for (int m = 0; m < 8; m++) SP[r * SPS + lane + 32 * m] = v[m] * inv;
            }
        }
        __syncthreads();

        // ---- P3: AV, (2-row, 8-v) lanes. warp = 16-j group.
        {
            const int j0 = warp * 16;
            const int r2 = (lane & 15) * 2;     // rows r2, r2+1
            const int v0 = (lane >> 4) * 8;     // v half
            u64 acc[8];                          // [2 rows][4 v-pairs]
#pragma unroll
            for (int v = 0; v < 8; v++) acc[v] = 0ull;
#pragma unroll
            for (int jj = 0; jj < 16; jj++) {
                const int j = j0 + jj;
                float pa = SP[r2 * SPS + j];
                float pb = SP[(r2 + 1) * SPS + j];
                u64 pa2 = pack2(pa, pa);
                u64 pb2 = pack2(pb, pb);
                const ulonglong2* vp = (const ulonglong2*)(sV + j * 16 + v0);
                ulonglong2 va = vp[0], vb = vp[1];
                acc[0] = fma2(pa2, va.x, acc[0]); acc[1] = fma2(pa2, va.y, acc[1]);
                acc[2] = fma2(pa2, vb.x, acc[2]); acc[3] = fma2(pa2, vb.y, acc[3]);
                acc[4] = fma2(pb2, va.x, acc[4]); acc[5] = fma2(pb2, va.y, acc[5]);
                acc[6] = fma2(pb2, vb.x, acc[6]); acc[7] = fma2(pb2, vb.y, acc[7]);
            }
            // RST=20 (mult of 4) => 16B-aligned for every row
            ulonglong2* rpa = (ulonglong2*)(red + (warp * 32 + r2) * RST + v0);
            ulonglong2* rpb = (ulonglong2*)(red + (warp * 32 + r2 + 1) * RST + v0);
            rpa[0] = make_ulonglong2(acc[0], acc[1]);
            rpa[1] = make_ulonglong2(acc[2], acc[3]);
            rpb[0] = make_ulonglong2(acc[4], acc[5]);
            rpb[1] = make_ulonglong2(acc[6], acc[7]);
        }
        __syncthreads();

        // ---- P4: sum 16 j-group partials (packed), write g_heads
        if (tid < 256) {
            const int r = tid >> 3, vp = tid & 7;
            u64 s = 0ull;
#pragma unroll
            for (int jq = 0; jq < 16; jq++)
                s = addp2(s, *(const u64*)(red + (jq * 32 + r) * RST + vp * 2));
            float2 f = unpack2(s);
            *(float2*)(g_heads + (size_t)(b * NN + itile + r) * HK + head * 16 + vp * 2) = f;
        }
    }
}

// =====================================================================
// host launcher
// =====================================================================
extern "C" void kernel_launch(void* const* d_in, const int* in_sizes, int n_in,
                              void* d_out, int out_size)
{
    (void)in_sizes; (void)n_in; (void)out_size;
    const float* q    = (const float*)d_in[0];
    const float* hx   = (const float*)d_in[1];
    const int*   mask = (const int*)d_in[2];
    const float* edge = (const float*)d_in[3];
    const float* Wq   = (const float*)d_in[4];
    const float* Wk   = (const float*)d_in[5];
    const float* Wv   = (const float*)d_in[6];
    const float* Wo   = (const float*)d_in[7];
    const float* mw1  = (const float*)d_in[8];
    const float* mb1  = (const float*)d_in[9];
    const float* mw2  = (const float*)d_in[10];
    const float* mb2  = (const float*)d_in[11];
    const float* mw3  = (const float*)d_in[12];
    const float* mb3  = (const float*)d_in[13];

    const int smem_gemm = (128 * 128 + 64 * AS) * 4;
    const int smem_attn = 23680 * 4;   // 94,720 B

    cudaFuncSetAttribute(gemm_qkv_kernel,   cudaFuncAttributeMaxDynamicSharedMemorySize, smem_gemm);
    cudaFuncSetAttribute(gemm_out_kernel,   cudaFuncAttributeMaxDynamicSharedMemorySize, smem_gemm);
    cudaFuncSetAttribute(attn_fused_kernel, cudaFuncAttributeMaxDynamicSharedMemorySize, smem_attn);

    pwl_build_kernel<<<1, 512>>>(mw1, mb1, mw2, mb2, mw3, mb3);

    gemm_qkv_kernel<<<dim3(ROWS / 64, 3), 256, smem_gemm>>>(q, hx, Wq, Wk, Wv);

    seg_kernel<<<(BB * NN * NN) / (512 * 4), 512>>>(edge, mask);

    attn_fused_kernel<<<dim3(32, BB), 512, smem_attn>>>(edge);

    gemm_out_kernel<<<ROWS / 64, 256, smem_gemm>>>(Wo, (float*)d_out);
}

// round 14
// speedup vs baseline: 1.2223x; 1.0075x over previous
#include <cuda_runtime.h>
#include <math.h>
#include <stdint.h>

// Problem constants
#define BB   128
#define NN   256
#define DIN  128
#define HH   8
#define DK   16
#define HK   128
#define ROWS (BB*NN)        // 32768
#define NORMC 0.25f
#define AS   132            // GEMM A smem stride
#define SPS  257            // score/prob row stride (odd => conflict-free)
#define RST  20             // red row stride (multiple of 4 => 16B-aligned rows)

typedef unsigned long long u64;

// ---- f32x2 packed math ----
__device__ __forceinline__ u64 pack2(float a, float b) {
    u64 r; asm("mov.b64 %0, {%1, %2};" : "=l"(r) : "f"(a), "f"(b)); return r;
}
__device__ __forceinline__ u64 fma2(u64 a, u64 b, u64 c) {
    u64 d; asm("fma.rn.f32x2 %0, %1, %2, %3;" : "=l"(d) : "l"(a), "l"(b), "l"(c)); return d;
}
__device__ __forceinline__ u64 addp2(u64 a, u64 b) {
    u64 d; asm("add.rn.f32x2 %0, %1, %2;" : "=l"(d) : "l"(a), "l"(b)); return d;
}
__device__ __forceinline__ float2 unpack2(u64 v) {
    float2 f; asm("mov.b64 {%0, %1}, %2;" : "=f"(f.x), "=f"(f.y) : "l"(v)); return f;
}

// ---------------- device-global scratch ----------------
// Q/K/V head-major: [h][b*N+n][16]
__device__ float g_Q[(size_t)HH * ROWS * DK];
__device__ float g_K[(size_t)HH * ROWS * DK];
__device__ float g_V[(size_t)HH * ROWS * DK];
__device__ float g_heads[(size_t)ROWS * HK];

__device__ float g_breaks[512];
__device__ float g_tab[512 * 16];
__device__ unsigned short g_seg[(size_t)BB * NN * NN]; // seg | mask<<15

// =====================================================================
// PWL build (one block, 512 threads)
// =====================================================================
__global__ void pwl_build_kernel(const float* __restrict__ mw1, const float* __restrict__ mb1,
                                 const float* __restrict__ mw2, const float* __restrict__ mb2,
                                 const float* __restrict__ mw3, const float* __restrict__ mb3)
{
    __shared__ float w1[16], b1[16], w2[256], b2[16], w3[128], b3[8];
    __shared__ float tsort[16];
    __shared__ float cand[512];
    __shared__ int   cnt;

    const int tid = threadIdx.x;
    if (tid < 16)  { w1[tid] = mw1[tid]; b1[tid] = mb1[tid]; b2[tid] = mb2[tid]; }
    if (tid < 256) w2[tid] = mw2[tid];
    if (tid < 128) w3[tid] = mw3[tid];
    if (tid < 8)   b3[tid] = mb3[tid];
    cand[tid] = 3.0e38f;
    if (tid == 0) cnt = 16;
    __syncthreads();

    if (tid < 16) {
        float t = (w1[tid] != 0.f) ? (-b1[tid] / w1[tid]) : 3.0e38f;
        cand[tid] = t;
    }
    __syncthreads();
    if (tid == 0) {
        for (int i = 0; i < 16; i++) tsort[i] = cand[i];
        for (int i = 1; i < 16; i++) {
            float v = tsort[i]; int k = i - 1;
            while (k >= 0 && tsort[k] > v) { tsort[k + 1] = tsort[k]; k--; }
            tsort[k + 1] = v;
        }
    }
    __syncthreads();

    if (tid < 17 * 16) {
        int iv = tid >> 4, c = tid & 15;
        float lo = (iv == 0)  ? -3.0e38f : tsort[iv - 1];
        float hi = (iv == 16) ?  3.0e38f : tsort[iv];
        if (lo < hi) {
            float m;
            if (lo <= -1e30f && hi >= 1e30f) m = 0.f;
            else if (lo <= -1e30f)           m = hi - 1.f;
            else if (hi >=  1e30f)           m = lo + 1.f;
            else                             m = 0.5f * (lo + hi);
            float g = 0.f, q = b2[c];
            for (int n = 0; n < 16; n++) {
                if (fmaf(m, w1[n], b1[n]) > 0.f) {
                    g = fmaf(w1[n], w2[n * 16 + c], g);
                    q = fmaf(b1[n], w2[n * 16 + c], q);
                }
            }
            if (g != 0.f) {
                float x = -q / g;
                if (x > lo && x < hi && fabsf(x) < 1e30f) {
                    int k = atomicAdd(&cnt, 1);
                    cand[k] = x;
                }
            }
        }
    }
    __syncthreads();
    const int ncand = cnt;

    for (int k = 2; k <= 512; k <<= 1) {
        for (int j = k >> 1; j > 0; j >>= 1) {
            int ixj = tid ^ j;
            if (ixj > tid) {
                bool up = (tid & k) == 0;
                float a = cand[tid], b = cand[ixj];
                if ((a > b) == up) { cand[tid] = b; cand[ixj] = a; }
            }
            __syncthreads();
        }
    }

    g_breaks[tid] = (tid < ncand) ? cand[tid] : 3.0e38f;

    if (tid <= ncand) {
        float lo = (tid == 0)     ? -3.0e38f : cand[tid - 1];
        float hi = (tid == ncand) ?  3.0e38f : cand[tid];
        float m;
        if (lo <= -1e30f && hi >= 1e30f) m = 0.f;
        else if (lo <= -1e30f)           m = hi - 1.f;
        else if (hi >=  1e30f)           m = lo + 1.f;
        else                             m = 0.5f * (lo + hi);

        float slope[8], inter[8];
        for (int h = 0; h < 8; h++) { slope[h] = 0.f; inter[h] = b3[h]; }
        for (int c = 0; c < 16; c++) {
            float gc = 0.f, qc = b2[c];
            for (int n = 0; n < 16; n++) {
                if (fmaf(m, w1[n], b1[n]) > 0.f) {
                    gc = fmaf(w1[n], w2[n * 16 + c], gc);
                    qc = fmaf(b1[n], w2[n * 16 + c], qc);
                }
            }
            if (fmaf(gc, m, qc) > 0.f) {
                for (int h = 0; h < 8; h++) {
                    slope[h] = fmaf(gc, w3[c * 8 + h], slope[h]);
                    inter[h] = fmaf(qc, w3[c * 8 + h], inter[h]);
                }
            }
        }
        for (int h = 0; h < 8; h++) {
            g_tab[tid * 16 + h * 2]     = slope[h];
            g_tab[tid * 16 + h * 2 + 1] = inter[h];
        }
    }
}

// =====================================================================
// GEMM body, f32x2 inner loop (as R11)
// =====================================================================
__device__ __forceinline__ void gemm_body(const float* __restrict__ A,
                                          const float* __restrict__ Wraw,
                                          float* __restrict__ Out,
                                          int mode, int row0)
{
    extern __shared__ float sm[];
    float* Wsm = sm;
    float* Asm = sm + 128 * 128;

    const int tid = threadIdx.x;

    for (int i4 = tid; i4 < 4096; i4 += 256) {
        int d = i4 >> 5, c4 = (i4 & 31) * 4;
        float4 w;
        if (mode == 0) w = *(const float4*)(Wraw + (c4 >> 4) * (DIN * 16) + d * 16 + (c4 & 15));
        else           w = *(const float4*)(Wraw + d * 128 + c4);
        *(float4*)(Wsm + d * 128 + c4) = w;
    }
    for (int i4 = tid; i4 < 2048; i4 += 256) {
        int r = i4 >> 5, c4 = (i4 & 31) * 4;
        *(float4*)(Asm + r * AS + c4) = *(const float4*)(A + (size_t)(row0 + r) * 128 + c4);
    }
    __syncthreads();

    const int tx = tid & 15, ty = tid >> 4;
    const int ca = tx * 4;
    const int r0 = ty * 4;
    u64 acc2[4][4];
#pragma unroll
    for (int u = 0; u < 4; u++)
#pragma unroll
        for (int k = 0; k < 4; k++) acc2[u][k] = 0ull;

#pragma unroll 2
    for (int dc = 0; dc < 128; dc += 4) {
        float4 a4[4];
#pragma unroll
        for (int u = 0; u < 4; u++) a4[u] = *(const float4*)(Asm + (r0 + u) * AS + dc);
#pragma unroll
        for (int dd = 0; dd < 4; dd++) {
            ulonglong2 w0 = *(const ulonglong2*)(Wsm + (dc + dd) * 128 + ca);
            ulonglong2 w1 = *(const ulonglong2*)(Wsm + (dc + dd) * 128 + 64 + ca);
#pragma unroll
            for (int u = 0; u < 4; u++) {
                float a = (dd == 0) ? a4[u].x : (dd == 1) ? a4[u].y : (dd == 2) ? a4[u].z : a4[u].w;
                u64 a2 = pack2(a, a);
                acc2[u][0] = fma2(a2, w0.x, acc2[u][0]);
                acc2[u][1] = fma2(a2, w0.y, acc2[u][1]);
                acc2[u][2] = fma2(a2, w1.x, acc2[u][2]);
                acc2[u][3] = fma2(a2, w1.y, acc2[u][3]);
            }
        }
    }
#pragma unroll
    for (int u = 0; u < 4; u++) {
        float2 p0 = unpack2(acc2[u][0]), p1 = unpack2(acc2[u][1]);
        float2 p2 = unpack2(acc2[u][2]), p3 = unpack2(acc2[u][3]);
        float4 o0 = {p0.x, p0.y, p1.x, p1.y};
        float4 o1 = {p2.x, p2.y, p3.x, p3.y};
        const int row = row0 + r0 + u;
        if (mode == 0) {
            int h0 = ca >> 4, h1 = (64 + ca) >> 4;
            *(float4*)(Out + ((size_t)h0 * ROWS + row) * 16 + (ca & 15)) = o0;
            *(float4*)(Out + ((size_t)h1 * ROWS + row) * 16 + (ca & 15)) = o1;
        } else {
            float* orow = Out + (size_t)row * 128;
            *(float4*)(orow + ca)      = o0;
            *(float4*)(orow + 64 + ca) = o1;
        }
    }
}

// =====================================================================
// gemm_qkv + seg fused launch: z<3 = QKV projections; z==3 = seg search
// (seg is DRAM-bound and overlaps with the FMA-bound gemm blocks)
// =====================================================================
__global__ void __launch_bounds__(256) gemm_qkv_seg_kernel(const float* __restrict__ q,
                                                           const float* __restrict__ hx,
                                                           const float* __restrict__ Wq,
                                                           const float* __restrict__ Wk,
                                                           const float* __restrict__ Wv,
                                                           const float* __restrict__ Ebm,
                                                           const int* __restrict__ mask)
{
    const int z = blockIdx.y;
    if (z == 3) {
        extern __shared__ float smf[];
        float* sB = smf;
        const int tid = threadIdx.x;
        for (int i = tid; i < 512; i += 256) sB[i] = g_breaks[i];
        __syncthreads();
        const size_t stride = 512 * 256;
        size_t base = (size_t)blockIdx.x * 256 + tid;
#pragma unroll 2
        for (int it = 0; it < 16; it++) {
            size_t v = base + (size_t)it * stride;
            float4 e4 = ((const float4*)Ebm)[v];
            int4   m4 = ((const int4*)mask)[v];
            const float ev[4] = {e4.x, e4.y, e4.z, e4.w};
            const int   mv[4] = {m4.x, m4.y, m4.z, m4.w};
            unsigned short ov[4];
#pragma unroll
            for (int p = 0; p < 4; p++) {
                float e = ev[p];
                int seg = 0;
#pragma unroll
                for (int st = 256; st >= 1; st >>= 1) {
                    int cnd = seg + st;
                    if (e >= sB[cnd - 1]) seg = cnd;
                }
                ov[p] = (unsigned short)(seg | (mv[p] ? 0x8000 : 0));
            }
            ushort4 out; out.x = ov[0]; out.y = ov[1]; out.z = ov[2]; out.w = ov[3];
            ((ushort4*)g_seg)[v] = out;
        }
        return;
    }
    const float* A = (z == 0) ? q : hx;
    const float* W = (z == 0) ? Wq : (z == 1) ? Wk : Wv;
    float* Out = (z == 0) ? g_Q : (z == 1) ? g_K : g_V;
    gemm_body(A, W, Out, 0, blockIdx.x * 64);
}

__global__ void __launch_bounds__(256) gemm_out_kernel(const float* __restrict__ Wo,
                                                       float* __restrict__ Out)
{
    gemm_body(g_heads, Wo, Out, 1, blockIdx.x * 64);
}

// =====================================================================
// Fused attention v9: fma2 P1 dot; deferred normalization (inv in P4).
// Block = (b, 64-row region, head). 512 threads, 2 blocks/SM.
// smem (floats): SP 32x257=8224 | red 16x32x20=10240 | V 4096 | Q 512
//                | sT 608 | sInv 32  total 23712 f = 94,848 B
// =====================================================================
__global__ void __launch_bounds__(512, 2)
attn_fused_kernel(const float* __restrict__ Ebm)
{
    extern __shared__ float sm[];
    float* SP   = sm;                 // [32][257] scores -> unnormalized probs
    float* red  = SP + 8224;          // [16][32][20]
    float* sV   = red + 10240;        // [256][16]
    float* Qsm  = sV + 4096;          // [32][16] (pre-scaled by NORMC)
    float* sT   = Qsm + 512;          // [304][2] slope/inter for this head
    float* sInv = sT + 608;           // [32] per-row 1/sum

    const int tid    = threadIdx.x;
    const int b      = blockIdx.y;
    const int itile0 = (blockIdx.x & 3) * 64;   // 64-row region
    const int head   = blockIdx.x >> 2;

    const size_t hbase = (size_t)head * ROWS + (size_t)b * NN;

    const int warp = tid >> 5, lane = tid & 31;
    const int jq8 = warp & 7;
    const int jgl = jq8 * 32 + lane;
    const int rh  = warp >> 3;

    // ---- K into packed registers (reused across both tiles)
    u64 K2[8];
    {
        const ulonglong2* Kg = (const ulonglong2*)(g_K + (hbase + jgl) * 16);
#pragma unroll
        for (int qq = 0; qq < 4; qq++) {
            ulonglong2 kv = Kg[qq];
            K2[qq * 2]     = kv.x;
            K2[qq * 2 + 1] = kv.y;
        }
    }

    // ---- stage V (contiguous), per-head table (once per block)
    {
        const float4* Vg = (const float4*)(g_V + hbase * 16);
#pragma unroll
        for (int p = 0; p < 2; p++) {
            int q4 = tid + 512 * p;
            *(float4*)(sV + q4 * 4) = Vg[q4];
        }
        if (tid < 304) {
            sT[tid * 2]     = g_tab[tid * 16 + head * 2];
            sT[tid * 2 + 1] = g_tab[tid * 16 + head * 2 + 1];
        }
    }

    for (int tile = 0; tile < 2; tile++) {
        const int itile = itile0 + tile * 32;

        // ---- stage Q (scaled) for this tile
        __syncthreads();   // (first iter: covers V/sT staging; later: red reads done)
        if (tid < 128) {
            float4 qv = *(const float4*)(g_Q + (hbase + itile) * 16 + tid * 4);
            qv.x *= NORMC; qv.y *= NORMC; qv.z *= NORMC; qv.w *= NORMC;
            *(float4*)(Qsm + tid * 4) = qv;
        }
        __syncthreads();

        // ---- P1: SP = bias(e) + Q.K  (packed dot; e/seg prefetched 1 row ahead)
        {
            const size_t gbase = (size_t)(b * NN + itile) * NN + jgl;
            const int rbase = rh * 16;

            float e_nxt = Ebm[gbase + (size_t)rbase * NN];
            unsigned short s_nxt = g_seg[gbase + (size_t)rbase * NN];

#pragma unroll 4
            for (int rr = 0; rr < 16; rr++) {
                const int r = rbase + rr;
                float e_cur = e_nxt;
                unsigned short s_cur = s_nxt;
                if (rr < 15) {
                    e_nxt = Ebm[gbase + (size_t)(r + 1) * NN];
                    s_nxt = g_seg[gbase + (size_t)(r + 1) * NN];
                }
                const ulonglong2* qp = (const ulonglong2*)(Qsm + r * 16);
                ulonglong2 qa = qp[0], qb = qp[1], qc = qp[2], qd = qp[3];
                u64 d2 = 0ull;
                d2 = fma2(qa.x, K2[0], d2); d2 = fma2(qa.y, K2[1], d2);
                d2 = fma2(qb.x, K2[2], d2); d2 = fma2(qb.y, K2[3], d2);
                d2 = fma2(qc.x, K2[4], d2); d2 = fma2(qc.y, K2[5], d2);
                d2 = fma2(qd.x, K2[6], d2); d2 = fma2(qd.y, K2[7], d2);
                float2 df = unpack2(d2);
                float d = df.x + df.y;

                int seg = s_cur & 0x7fff;
                float2 t = *(const float2*)(sT + seg * 2);
                float bias = (s_cur & 0x8000) ? -INFINITY : fmaf(t.x, e_cur, t.y);
                SP[r * SPS + jgl] = bias + d;       // -inf + d = -inf
            }
        }
        __syncthreads();

        // ---- P2: softmax (unnormalized exp stored; inv saved per row)
        {
#pragma unroll
            for (int rr = 0; rr < 2; rr++) {
                const int r = warp * 2 + rr;
                float v[8];
#pragma unroll
                for (int m = 0; m < 8; m++) v[m] = SP[r * SPS + lane + 32 * m];
                float mx = v[0];
#pragma unroll
                for (int m = 1; m < 8; m++) mx = fmaxf(mx, v[m]);
#pragma unroll
                for (int o = 16; o > 0; o >>= 1) mx = fmaxf(mx, __shfl_xor_sync(0xffffffffu, mx, o));
                float s = 0.f;
#pragma unroll
                for (int m = 0; m < 8; m++) { v[m] = __expf(v[m] - mx); s += v[m]; }
#pragma unroll
                for (int o = 16; o > 0; o >>= 1) s += __shfl_xor_sync(0xffffffffu, s, o);
                if (lane == 0) sInv[r] = 1.f / s;
#pragma unroll
                for (int m = 0; m < 8; m++) SP[r * SPS + lane + 32 * m] = v[m];
            }
        }
        __syncthreads();

        // ---- P3: AV (unnormalized), (2-row, 8-v) lanes. warp = 16-j group.
        {
            const int j0 = warp * 16;
            const int r2 = (lane & 15) * 2;     // rows r2, r2+1
            const int v0 = (lane >> 4) * 8;     // v half
            u64 acc[8];                          // [2 rows][4 v-pairs]
#pragma unroll
            for (int v = 0; v < 8; v++) acc[v] = 0ull;
#pragma unroll
            for (int jj = 0; jj < 16; jj++) {
                const int j = j0 + jj;
                float pa = SP[r2 * SPS + j];
                float pb = SP[(r2 + 1) * SPS + j];
                u64 pa2 = pack2(pa, pa);
                u64 pb2 = pack2(pb, pb);
                const ulonglong2* vp = (const ulonglong2*)(sV + j * 16 + v0);
                ulonglong2 va = vp[0], vb = vp[1];
                acc[0] = fma2(pa2, va.x, acc[0]); acc[1] = fma2(pa2, va.y, acc[1]);
                acc[2] = fma2(pa2, vb.x, acc[2]); acc[3] = fma2(pa2, vb.y, acc[3]);
                acc[4] = fma2(pb2, va.x, acc[4]); acc[5] = fma2(pb2, va.y, acc[5]);
                acc[6] = fma2(pb2, vb.x, acc[6]); acc[7] = fma2(pb2, vb.y, acc[7]);
            }
            ulonglong2* rpa = (ulonglong2*)(red + (warp * 32 + r2) * RST + v0);
            ulonglong2* rpb = (ulonglong2*)(red + (warp * 32 + r2 + 1) * RST + v0);
            rpa[0] = make_ulonglong2(acc[0], acc[1]);
            rpa[1] = make_ulonglong2(acc[2], acc[3]);
            rpb[0] = make_ulonglong2(acc[4], acc[5]);
            rpb[1] = make_ulonglong2(acc[6], acc[7]);
        }
        __syncthreads();

        // ---- P4: sum 16 j-group partials (packed), normalize, write g_heads
        if (tid < 256) {
            const int r = tid >> 3, vp = tid & 7;
            u64 s = 0ull;
#pragma unroll
            for (int jq = 0; jq < 16; jq++)
                s = addp2(s, *(const u64*)(red + (jq * 32 + r) * RST + vp * 2));
            float inv = sInv[r];
            float2 f = unpack2(s);
            f.x *= inv; f.y *= inv;
            *(float2*)(g_heads + (size_t)(b * NN + itile + r) * HK + head * 16 + vp * 2) = f;
        }
    }
}

// =====================================================================
// host launcher
// =====================================================================
extern "C" void kernel_launch(void* const* d_in, const int* in_sizes, int n_in,
                              void* d_out, int out_size)
{
    (void)in_sizes; (void)n_in; (void)out_size;
    const float* q    = (const float*)d_in[0];
    const float* hx   = (const float*)d_in[1];
    const int*   mask = (const int*)d_in[2];
    const float* edge = (const float*)d_in[3];
    const float* Wq   = (const float*)d_in[4];
    const float* Wk   = (const float*)d_in[5];
    const float* Wv   = (const float*)d_in[6];
    const float* Wo   = (const float*)d_in[7];
    const float* mw1  = (const float*)d_in[8];
    const float* mb1  = (const float*)d_in[9];
    const float* mw2  = (const float*)d_in[10];
    const float* mb2  = (const float*)d_in[11];
    const float* mw3  = (const float*)d_in[12];
    const float* mb3  = (const float*)d_in[13];

    const int smem_gemm = (128 * 128 + 64 * AS) * 4;
    const int smem_attn = 23712 * 4;   // 94,848 B

    cudaFuncSetAttribute(gemm_qkv_seg_kernel, cudaFuncAttributeMaxDynamicSharedMemorySize, smem_gemm);
    cudaFuncSetAttribute(gemm_out_kernel,     cudaFuncAttributeMaxDynamicSharedMemorySize, smem_gemm);
    cudaFuncSetAttribute(attn_fused_kernel,   cudaFuncAttributeMaxDynamicSharedMemorySize, smem_attn);

    pwl_build_kernel<<<1, 512>>>(mw1, mb1, mw2, mb2, mw3, mb3);

    // QKV projections + seg search in one launch (z==3 = seg)
    gemm_qkv_seg_kernel<<<dim3(ROWS / 64, 4), 256, smem_gemm>>>(q, hx, Wq, Wk, Wv, edge, mask);

    attn_fused_kernel<<<dim3(32, BB), 512, smem_attn>>>(edge);

    gemm_out_kernel<<<ROWS / 64, 256, smem_gemm>>>(Wo, (float*)d_out);
}

// round 15
// speedup vs baseline: 1.2272x; 1.0040x over previous
#include <cuda_runtime.h>
#include <math.h>
#include <stdint.h>

// Problem constants
#define BB   128
#define NN   256
#define DIN  128
#define HH   8
#define DK   16
#define HK   128
#define ROWS (BB*NN)        // 32768
#define NORMC 0.25f
#define SPS  257            // score/prob row stride (odd => conflict-free)
#define RST  20             // red row stride (multiple of 4 => 16B-aligned rows)

typedef unsigned long long u64;

// ---- f32x2 packed math ----
__device__ __forceinline__ u64 pack2(float a, float b) {
    u64 r; asm("mov.b64 %0, {%1, %2};" : "=l"(r) : "f"(a), "f"(b)); return r;
}
__device__ __forceinline__ u64 fma2(u64 a, u64 b, u64 c) {
    u64 d; asm("fma.rn.f32x2 %0, %1, %2, %3;" : "=l"(d) : "l"(a), "l"(b), "l"(c)); return d;
}
__device__ __forceinline__ u64 addp2(u64 a, u64 b) {
    u64 d; asm("add.rn.f32x2 %0, %1, %2;" : "=l"(d) : "l"(a), "l"(b)); return d;
}
__device__ __forceinline__ float2 unpack2(u64 v) {
    float2 f; asm("mov.b64 {%0, %1}, %2;" : "=f"(f.x), "=f"(f.y) : "l"(v)); return f;
}

// ---------------- device-global scratch ----------------
// Q/K/V head-major: [h][b*N+n][16]
__device__ float g_Q[(size_t)HH * ROWS * DK];
__device__ float g_K[(size_t)HH * ROWS * DK];
__device__ float g_V[(size_t)HH * ROWS * DK];
__device__ float g_heads[(size_t)ROWS * HK];

__device__ float g_breaks[512];
__device__ float g_tab[512 * 16];
__device__ unsigned short g_seg[(size_t)BB * NN * NN]; // seg | mask<<15

// =====================================================================
// PWL build (one block, 512 threads)
// =====================================================================
__global__ void pwl_build_kernel(const float* __restrict__ mw1, const float* __restrict__ mb1,
                                 const float* __restrict__ mw2, const float* __restrict__ mb2,
                                 const float* __restrict__ mw3, const float* __restrict__ mb3)
{
    __shared__ float w1[16], b1[16], w2[256], b2[16], w3[128], b3[8];
    __shared__ float tsort[16];
    __shared__ float cand[512];
    __shared__ int   cnt;

    const int tid = threadIdx.x;
    if (tid < 16)  { w1[tid] = mw1[tid]; b1[tid] = mb1[tid]; b2[tid] = mb2[tid]; }
    if (tid < 256) w2[tid] = mw2[tid];
    if (tid < 128) w3[tid] = mw3[tid];
    if (tid < 8)   b3[tid] = mb3[tid];
    cand[tid] = 3.0e38f;
    if (tid == 0) cnt = 16;
    __syncthreads();

    if (tid < 16) {
        float t = (w1[tid] != 0.f) ? (-b1[tid] / w1[tid]) : 3.0e38f;
        cand[tid] = t;
    }
    __syncthreads();
    if (tid == 0) {
        for (int i = 0; i < 16; i++) tsort[i] = cand[i];
        for (int i = 1; i < 16; i++) {
            float v = tsort[i]; int k = i - 1;
            while (k >= 0 && tsort[k] > v) { tsort[k + 1] = tsort[k]; k--; }
            tsort[k + 1] = v;
        }
    }
    __syncthreads();

    if (tid < 17 * 16) {
        int iv = tid >> 4, c = tid & 15;
        float lo = (iv == 0)  ? -3.0e38f : tsort[iv - 1];
        float hi = (iv == 16) ?  3.0e38f : tsort[iv];
        if (lo < hi) {
            float m;
            if (lo <= -1e30f && hi >= 1e30f) m = 0.f;
            else if (lo <= -1e30f)           m = hi - 1.f;
            else if (hi >=  1e30f)           m = lo + 1.f;
            else                             m = 0.5f * (lo + hi);
            float g = 0.f, q = b2[c];
            for (int n = 0; n < 16; n++) {
                if (fmaf(m, w1[n], b1[n]) > 0.f) {
                    g = fmaf(w1[n], w2[n * 16 + c], g);
                    q = fmaf(b1[n], w2[n * 16 + c], q);
                }
            }
            if (g != 0.f) {
                float x = -q / g;
                if (x > lo && x < hi && fabsf(x) < 1e30f) {
                    int k = atomicAdd(&cnt, 1);
                    cand[k] = x;
                }
            }
        }
    }
    __syncthreads();
    const int ncand = cnt;

    for (int k = 2; k <= 512; k <<= 1) {
        for (int j = k >> 1; j > 0; j >>= 1) {
            int ixj = tid ^ j;
            if (ixj > tid) {
                bool up = (tid & k) == 0;
                float a = cand[tid], b = cand[ixj];
                if ((a > b) == up) { cand[tid] = b; cand[ixj] = a; }
            }
            __syncthreads();
        }
    }

    g_breaks[tid] = (tid < ncand) ? cand[tid] : 3.0e38f;

    if (tid <= ncand) {
        float lo = (tid == 0)     ? -3.0e38f : cand[tid - 1];
        float hi = (tid == ncand) ?  3.0e38f : cand[tid];
        float m;
        if (lo <= -1e30f && hi >= 1e30f) m = 0.f;
        else if (lo <= -1e30f)           m = hi - 1.f;
        else if (hi >=  1e30f)           m = lo + 1.f;
        else                             m = 0.5f * (lo + hi);

        float slope[8], inter[8];
        for (int h = 0; h < 8; h++) { slope[h] = 0.f; inter[h] = b3[h]; }
        for (int c = 0; c < 16; c++) {
            float gc = 0.f, qc = b2[c];
            for (int n = 0; n < 16; n++) {
                if (fmaf(m, w1[n], b1[n]) > 0.f) {
                    gc = fmaf(w1[n], w2[n * 16 + c], gc);
                    qc = fmaf(b1[n], w2[n * 16 + c], qc);
                }
            }
            if (fmaf(gc, m, qc) > 0.f) {
                for (int h = 0; h < 8; h++) {
                    slope[h] = fmaf(gc, w3[c * 8 + h], slope[h]);
                    inter[h] = fmaf(qc, w3[c * 8 + h], inter[h]);
                }
            }
        }
        for (int h = 0; h < 8; h++) {
            g_tab[tid * 16 + h * 2]     = slope[h];
            g_tab[tid * 16 + h * 2 + 1] = inter[h];
        }
    }
}

// =====================================================================
// GEMM body v2: W in smem (64KB); A streamed from global via L1.
// 3 blocks/SM. 64 rows x 128 cols per block, per-thread 4x8.
// =====================================================================
__device__ __forceinline__ void gemm_body(const float* __restrict__ A,
                                          const float* __restrict__ Wraw,
                                          float* __restrict__ Out,
                                          int mode, int row0)
{
    extern __shared__ float sm[];
    float* Wsm = sm;   // [128][128]

    const int tid = threadIdx.x;

    for (int i4 = tid; i4 < 4096; i4 += 256) {
        int d = i4 >> 5, c4 = (i4 & 31) * 4;
        float4 w;
        if (mode == 0) w = *(const float4*)(Wraw + (c4 >> 4) * (DIN * 16) + d * 16 + (c4 & 15));
        else           w = *(const float4*)(Wraw + d * 128 + c4);
        *(float4*)(Wsm + d * 128 + c4) = w;
    }
    __syncthreads();

    const int tx = tid & 15, ty = tid >> 4;
    const int ca = tx * 4;
    const int r0 = ty * 4;

    const float* A0 = A + (size_t)(row0 + r0) * 128;
    const float* A1 = A0 + 128;
    const float* A2 = A1 + 128;
    const float* A3 = A2 + 128;

    u64 acc2[4][4];
#pragma unroll
    for (int u = 0; u < 4; u++)
#pragma unroll
        for (int k = 0; k < 4; k++) acc2[u][k] = 0ull;

#pragma unroll 2
    for (int dc = 0; dc < 128; dc += 4) {
        float4 a4[4];
        a4[0] = *(const float4*)(A0 + dc);
        a4[1] = *(const float4*)(A1 + dc);
        a4[2] = *(const float4*)(A2 + dc);
        a4[3] = *(const float4*)(A3 + dc);
#pragma unroll
        for (int dd = 0; dd < 4; dd++) {
            ulonglong2 w0 = *(const ulonglong2*)(Wsm + (dc + dd) * 128 + ca);
            ulonglong2 w1 = *(const ulonglong2*)(Wsm + (dc + dd) * 128 + 64 + ca);
#pragma unroll
            for (int u = 0; u < 4; u++) {
                float a = (dd == 0) ? a4[u].x : (dd == 1) ? a4[u].y : (dd == 2) ? a4[u].z : a4[u].w;
                u64 a2 = pack2(a, a);
                acc2[u][0] = fma2(a2, w0.x, acc2[u][0]);
                acc2[u][1] = fma2(a2, w0.y, acc2[u][1]);
                acc2[u][2] = fma2(a2, w1.x, acc2[u][2]);
                acc2[u][3] = fma2(a2, w1.y, acc2[u][3]);
            }
        }
    }
#pragma unroll
    for (int u = 0; u < 4; u++) {
        float2 p0 = unpack2(acc2[u][0]), p1 = unpack2(acc2[u][1]);
        float2 p2 = unpack2(acc2[u][2]), p3 = unpack2(acc2[u][3]);
        float4 o0 = {p0.x, p0.y, p1.x, p1.y};
        float4 o1 = {p2.x, p2.y, p3.x, p3.y};
        const int row = row0 + r0 + u;
        if (mode == 0) {
            int h0 = ca >> 4, h1 = (64 + ca) >> 4;
            *(float4*)(Out + ((size_t)h0 * ROWS + row) * 16 + (ca & 15)) = o0;
            *(float4*)(Out + ((size_t)h1 * ROWS + row) * 16 + (ca & 15)) = o1;
        } else {
            float* orow = Out + (size_t)row * 128;
            *(float4*)(orow + ca)      = o0;
            *(float4*)(orow + 64 + ca) = o1;
        }
    }
}

// =====================================================================
// gemm_qkv + seg fused launch: z<3 = QKV projections; z==3 = seg search
// =====================================================================
__global__ void __launch_bounds__(256, 3) gemm_qkv_seg_kernel(const float* __restrict__ q,
                                                              const float* __restrict__ hx,
                                                              const float* __restrict__ Wq,
                                                              const float* __restrict__ Wk,
                                                              const float* __restrict__ Wv,
                                                              const float* __restrict__ Ebm,
                                                              const int* __restrict__ mask)
{
    const int z = blockIdx.y;
    if (z == 3) {
        extern __shared__ float smf[];
        float* sB = smf;
        const int tid = threadIdx.x;
        for (int i = tid; i < 512; i += 256) sB[i] = g_breaks[i];
        __syncthreads();
        const size_t stride = 512 * 256;
        size_t base = (size_t)blockIdx.x * 256 + tid;
#pragma unroll 2
        for (int it = 0; it < 16; it++) {
            size_t v = base + (size_t)it * stride;
            float4 e4 = ((const float4*)Ebm)[v];
            int4   m4 = ((const int4*)mask)[v];
            const float ev[4] = {e4.x, e4.y, e4.z, e4.w};
            const int   mv[4] = {m4.x, m4.y, m4.z, m4.w};
            unsigned short ov[4];
#pragma unroll
            for (int p = 0; p < 4; p++) {
                float e = ev[p];
                int seg = 0;
#pragma unroll
                for (int st = 256; st >= 1; st >>= 1) {
                    int cnd = seg + st;
                    if (e >= sB[cnd - 1]) seg = cnd;
                }
                ov[p] = (unsigned short)(seg | (mv[p] ? 0x8000 : 0));
            }
            ushort4 out; out.x = ov[0]; out.y = ov[1]; out.z = ov[2]; out.w = ov[3];
            ((ushort4*)g_seg)[v] = out;
        }
        return;
    }
    const float* A = (z == 0) ? q : hx;
    const float* W = (z == 0) ? Wq : (z == 1) ? Wk : Wv;
    float* Out = (z == 0) ? g_Q : (z == 1) ? g_K : g_V;
    gemm_body(A, W, Out, 0, blockIdx.x * 64);
}

__global__ void __launch_bounds__(256, 3) gemm_out_kernel(const float* __restrict__ Wo,
                                                          float* __restrict__ Out)
{
    gemm_body(g_heads, Wo, Out, 1, blockIdx.x * 64);
}

// =====================================================================
// Fused attention v9 (unchanged from R14)
// =====================================================================
__global__ void __launch_bounds__(512, 2)
attn_fused_kernel(const float* __restrict__ Ebm)
{
    extern __shared__ float sm[];
    float* SP   = sm;                 // [32][257]
    float* red  = SP + 8224;          // [16][32][20]
    float* sV   = red + 10240;        // [256][16]
    float* Qsm  = sV + 4096;          // [32][16]
    float* sT   = Qsm + 512;          // [304][2]
    float* sInv = sT + 608;           // [32]

    const int tid    = threadIdx.x;
    const int b      = blockIdx.y;
    const int itile0 = (blockIdx.x & 3) * 64;
    const int head   = blockIdx.x >> 2;

    const size_t hbase = (size_t)head * ROWS + (size_t)b * NN;

    const int warp = tid >> 5, lane = tid & 31;
    const int jq8 = warp & 7;
    const int jgl = jq8 * 32 + lane;
    const int rh  = warp >> 3;

    u64 K2[8];
    {
        const ulonglong2* Kg = (const ulonglong2*)(g_K + (hbase + jgl) * 16);
#pragma unroll
        for (int qq = 0; qq < 4; qq++) {
            ulonglong2 kv = Kg[qq];
            K2[qq * 2]     = kv.x;
            K2[qq * 2 + 1] = kv.y;
        }
    }

    {
        const float4* Vg = (const float4*)(g_V + hbase * 16);
#pragma unroll
        for (int p = 0; p < 2; p++) {
            int q4 = tid + 512 * p;
            *(float4*)(sV + q4 * 4) = Vg[q4];
        }
        if (tid < 304) {
            sT[tid * 2]     = g_tab[tid * 16 + head * 2];
            sT[tid * 2 + 1] = g_tab[tid * 16 + head * 2 + 1];
        }
    }

    for (int tile = 0; tile < 2; tile++) {
        const int itile = itile0 + tile * 32;

        __syncthreads();
        if (tid < 128) {
            float4 qv = *(const float4*)(g_Q + (hbase + itile) * 16 + tid * 4);
            qv.x *= NORMC; qv.y *= NORMC; qv.z *= NORMC; qv.w *= NORMC;
            *(float4*)(Qsm + tid * 4) = qv;
        }
        __syncthreads();

        // ---- P1
        {
            const size_t gbase = (size_t)(b * NN + itile) * NN + jgl;
            const int rbase = rh * 16;

            float e_nxt = Ebm[gbase + (size_t)rbase * NN];
            unsigned short s_nxt = g_seg[gbase + (size_t)rbase * NN];

#pragma unroll 4
            for (int rr = 0; rr < 16; rr++) {
                const int r = rbase + rr;
                float e_cur = e_nxt;
                unsigned short s_cur = s_nxt;
                if (rr < 15) {
                    e_nxt = Ebm[gbase + (size_t)(r + 1) * NN];
                    s_nxt = g_seg[gbase + (size_t)(r + 1) * NN];
                }
                const ulonglong2* qp = (const ulonglong2*)(Qsm + r * 16);
                ulonglong2 qa = qp[0], qb = qp[1], qc = qp[2], qd = qp[3];
                u64 d2 = 0ull;
                d2 = fma2(qa.x, K2[0], d2); d2 = fma2(qa.y, K2[1], d2);
                d2 = fma2(qb.x, K2[2], d2); d2 = fma2(qb.y, K2[3], d2);
                d2 = fma2(qc.x, K2[4], d2); d2 = fma2(qc.y, K2[5], d2);
                d2 = fma2(qd.x, K2[6], d2); d2 = fma2(qd.y, K2[7], d2);
                float2 df = unpack2(d2);
                float d = df.x + df.y;

                int seg = s_cur & 0x7fff;
                float2 t = *(const float2*)(sT + seg * 2);
                float bias = (s_cur & 0x8000) ? -INFINITY : fmaf(t.x, e_cur, t.y);
                SP[r * SPS + jgl] = bias + d;
            }
        }
        __syncthreads();

        // ---- P2
        {
#pragma unroll
            for (int rr = 0; rr < 2; rr++) {
                const int r = warp * 2 + rr;
                float v[8];
#pragma unroll
                for (int m = 0; m < 8; m++) v[m] = SP[r * SPS + lane + 32 * m];
                float mx = v[0];
#pragma unroll
                for (int m = 1; m < 8; m++) mx = fmaxf(mx, v[m]);
#pragma unroll
                for (int o = 16; o > 0; o >>= 1) mx = fmaxf(mx, __shfl_xor_sync(0xffffffffu, mx, o));
                float s = 0.f;
#pragma unroll
                for (int m = 0; m < 8; m++) { v[m] = __expf(v[m] - mx); s += v[m]; }
#pragma unroll
                for (int o = 16; o > 0; o >>= 1) s += __shfl_xor_sync(0xffffffffu, s, o);
                if (lane == 0) sInv[r] = 1.f / s;
#pragma unroll
                for (int m = 0; m < 8; m++) SP[r * SPS + lane + 32 * m] = v[m];
            }
        }
        __syncthreads();

        // ---- P3
        {
            const int j0 = warp * 16;
            const int r2 = (lane & 15) * 2;
            const int v0 = (lane >> 4) * 8;
            u64 acc[8];
#pragma unroll
            for (int v = 0; v < 8; v++) acc[v] = 0ull;
#pragma unroll
            for (int jj = 0; jj < 16; jj++) {
                const int j = j0 + jj;
                float pa = SP[r2 * SPS + j];
                float pb = SP[(r2 + 1) * SPS + j];
                u64 pa2 = pack2(pa, pa);
                u64 pb2 = pack2(pb, pb);
                const ulonglong2* vp = (const ulonglong2*)(sV + j * 16 + v0);
                ulonglong2 va = vp[0], vb = vp[1];
                acc[0] = fma2(pa2, va.x, acc[0]); acc[1] = fma2(pa2, va.y, acc[1]);
                acc[2] = fma2(pa2, vb.x, acc[2]); acc[3] = fma2(pa2, vb.y, acc[3]);
                acc[4] = fma2(pb2, va.x, acc[4]); acc[5] = fma2(pb2, va.y, acc[5]);
                acc[6] = fma2(pb2, vb.x, acc[6]); acc[7] = fma2(pb2, vb.y, acc[7]);
            }
            ulonglong2* rpa = (ulonglong2*)(red + (warp * 32 + r2) * RST + v0);
            ulonglong2* rpb = (ulonglong2*)(red + (warp * 32 + r2 + 1) * RST + v0);
            rpa[0] = make_ulonglong2(acc[0], acc[1]);
            rpa[1] = make_ulonglong2(acc[2], acc[3]);
            rpb[0] = make_ulonglong2(acc[4], acc[5]);
            rpb[1] = make_ulonglong2(acc[6], acc[7]);
        }
        __syncthreads();

        // ---- P4
        if (tid < 256) {
            const int r = tid >> 3, vp = tid & 7;
            u64 s = 0ull;
#pragma unroll
            for (int jq = 0; jq < 16; jq++)
                s = addp2(s, *(const u64*)(red + (jq * 32 + r) * RST + vp * 2));
            float inv = sInv[r];
            float2 f = unpack2(s);
            f.x *= inv; f.y *= inv;
            *(float2*)(g_heads + (size_t)(b * NN + itile + r) * HK + head * 16 + vp * 2) = f;
        }
    }
}

// =====================================================================
// host launcher
// =====================================================================
extern "C" void kernel_launch(void* const* d_in, const int* in_sizes, int n_in,
                              void* d_out, int out_size)
{
    (void)in_sizes; (void)n_in; (void)out_size;
    const float* q    = (const float*)d_in[0];
    const float* hx   = (const float*)d_in[1];
    const int*   mask = (const int*)d_in[2];
    const float* edge = (const float*)d_in[3];
    const float* Wq   = (const float*)d_in[4];
    const float* Wk   = (const float*)d_in[5];
    const float* Wv   = (const float*)d_in[6];
    const float* Wo   = (const float*)d_in[7];
    const float* mw1  = (const float*)d_in[8];
    const float* mb1  = (const float*)d_in[9];
    const float* mw2  = (const float*)d_in[10];
    const float* mb2  = (const float*)d_in[11];
    const float* mw3  = (const float*)d_in[12];
    const float* mb3  = (const float*)d_in[13];

    const int smem_gemm = 128 * 128 * 4;   // 65,536 B -> 3 blocks/SM
    const int smem_attn = 23712 * 4;       // 94,848 B -> 2 blocks/SM

    cudaFuncSetAttribute(gemm_qkv_seg_kernel, cudaFuncAttributeMaxDynamicSharedMemorySize, smem_gemm);
    cudaFuncSetAttribute(gemm_out_kernel,     cudaFuncAttributeMaxDynamicSharedMemorySize, smem_gemm);
    cudaFuncSetAttribute(attn_fused_kernel,   cudaFuncAttributeMaxDynamicSharedMemorySize, smem_attn);

    pwl_build_kernel<<<1, 512>>>(mw1, mb1, mw2, mb2, mw3, mb3);

    // QKV projections + seg search in one launch (z==3 = seg)
    gemm_qkv_seg_kernel<<<dim3(ROWS / 64, 4), 256, smem_gemm>>>(q, hx, Wq, Wk, Wv, edge, mask);

    attn_fused_kernel<<<dim3(32, BB), 512, smem_attn>>>(edge);

    gemm_out_kernel<<<ROWS / 64, 256, smem_gemm>>>(Wo, (float*)d_out);
}

// round 16
// speedup vs baseline: 1.2875x; 1.0492x over previous
#include <cuda_runtime.h>
#include <math.h>
#include <stdint.h>

// Problem constants
#define BB   128
#define NN   256
#define DIN  128
#define HH   8
#define DK   16
#define HK   128
#define ROWS (BB*NN)        // 32768
#define NORMC 0.25f
#define SPS  257            // score/prob row stride (odd => conflict-free)
#define RST  20             // red row stride (multiple of 4 => 16B-aligned rows)

typedef unsigned long long u64;

// ---- f32x2 packed math ----
__device__ __forceinline__ u64 pack2(float a, float b) {
    u64 r; asm("mov.b64 %0, {%1, %2};" : "=l"(r) : "f"(a), "f"(b)); return r;
}
__device__ __forceinline__ u64 fma2(u64 a, u64 b, u64 c) {
    u64 d; asm("fma.rn.f32x2 %0, %1, %2, %3;" : "=l"(d) : "l"(a), "l"(b), "l"(c)); return d;
}
__device__ __forceinline__ u64 addp2(u64 a, u64 b) {
    u64 d; asm("add.rn.f32x2 %0, %1, %2;" : "=l"(d) : "l"(a), "l"(b)); return d;
}
__device__ __forceinline__ float2 unpack2(u64 v) {
    float2 f; asm("mov.b64 {%0, %1}, %2;" : "=f"(f.x), "=f"(f.y) : "l"(v)); return f;
}

// ---------------- device-global scratch ----------------
// Q/K/V head-major: [h][b*N+n][16]
__device__ float g_Q[(size_t)HH * ROWS * DK];
__device__ float g_K[(size_t)HH * ROWS * DK];
__device__ float g_V[(size_t)HH * ROWS * DK];
__device__ float g_heads[(size_t)ROWS * HK];

__device__ float g_breaks[512];
__device__ float g_tab[512 * 16];
__device__ float2 g_es[(size_t)BB * NN * NN];   // {e, bits(seg|mask<<15)} 64MB

// =====================================================================
// PWL build (one block, 512 threads)
// =====================================================================
__global__ void pwl_build_kernel(const float* __restrict__ mw1, const float* __restrict__ mb1,
                                 const float* __restrict__ mw2, const float* __restrict__ mb2,
                                 const float* __restrict__ mw3, const float* __restrict__ mb3)
{
    __shared__ float w1[16], b1[16], w2[256], b2[16], w3[128], b3[8];
    __shared__ float tsort[16];
    __shared__ float cand[512];
    __shared__ int   cnt;

    const int tid = threadIdx.x;
    if (tid < 16)  { w1[tid] = mw1[tid]; b1[tid] = mb1[tid]; b2[tid] = mb2[tid]; }
    if (tid < 256) w2[tid] = mw2[tid];
    if (tid < 128) w3[tid] = mw3[tid];
    if (tid < 8)   b3[tid] = mb3[tid];
    cand[tid] = 3.0e38f;
    if (tid == 0) cnt = 16;
    __syncthreads();

    if (tid < 16) {
        float t = (w1[tid] != 0.f) ? (-b1[tid] / w1[tid]) : 3.0e38f;
        cand[tid] = t;
    }
    __syncthreads();
    if (tid == 0) {
        for (int i = 0; i < 16; i++) tsort[i] = cand[i];
        for (int i = 1; i < 16; i++) {
            float v = tsort[i]; int k = i - 1;
            while (k >= 0 && tsort[k] > v) { tsort[k + 1] = tsort[k]; k--; }
            tsort[k + 1] = v;
        }
    }
    __syncthreads();

    if (tid < 17 * 16) {
        int iv = tid >> 4, c = tid & 15;
        float lo = (iv == 0)  ? -3.0e38f : tsort[iv - 1];
        float hi = (iv == 16) ?  3.0e38f : tsort[iv];
        if (lo < hi) {
            float m;
            if (lo <= -1e30f && hi >= 1e30f) m = 0.f;
            else if (lo <= -1e30f)           m = hi - 1.f;
            else if (hi >=  1e30f)           m = lo + 1.f;
            else                             m = 0.5f * (lo + hi);
            float g = 0.f, q = b2[c];
            for (int n = 0; n < 16; n++) {
                if (fmaf(m, w1[n], b1[n]) > 0.f) {
                    g = fmaf(w1[n], w2[n * 16 + c], g);
                    q = fmaf(b1[n], w2[n * 16 + c], q);
                }
            }
            if (g != 0.f) {
                float x = -q / g;
                if (x > lo && x < hi && fabsf(x) < 1e30f) {
                    int k = atomicAdd(&cnt, 1);
                    cand[k] = x;
                }
            }
        }
    }
    __syncthreads();
    const int ncand = cnt;

    for (int k = 2; k <= 512; k <<= 1) {
        for (int j = k >> 1; j > 0; j >>= 1) {
            int ixj = tid ^ j;
            if (ixj > tid) {
                bool up = (tid & k) == 0;
                float a = cand[tid], b = cand[ixj];
                if ((a > b) == up) { cand[tid] = b; cand[ixj] = a; }
            }
            __syncthreads();
        }
    }

    g_breaks[tid] = (tid < ncand) ? cand[tid] : 3.0e38f;

    if (tid <= ncand) {
        float lo = (tid == 0)     ? -3.0e38f : cand[tid - 1];
        float hi = (tid == ncand) ?  3.0e38f : cand[tid];
        float m;
        if (lo <= -1e30f && hi >= 1e30f) m = 0.f;
        else if (lo <= -1e30f)           m = hi - 1.f;
        else if (hi >=  1e30f)           m = lo + 1.f;
        else                             m = 0.5f * (lo + hi);

        float slope[8], inter[8];
        for (int h = 0; h < 8; h++) { slope[h] = 0.f; inter[h] = b3[h]; }
        for (int c = 0; c < 16; c++) {
            float gc = 0.f, qc = b2[c];
            for (int n = 0; n < 16; n++) {
                if (fmaf(m, w1[n], b1[n]) > 0.f) {
                    gc = fmaf(w1[n], w2[n * 16 + c], gc);
                    qc = fmaf(b1[n], w2[n * 16 + c], qc);
                }
            }
            if (fmaf(gc, m, qc) > 0.f) {
                for (int h = 0; h < 8; h++) {
                    slope[h] = fmaf(gc, w3[c * 8 + h], slope[h]);
                    inter[h] = fmaf(qc, w3[c * 8 + h], inter[h]);
                }
            }
        }
        for (int h = 0; h < 8; h++) {
            g_tab[tid * 16 + h * 2]     = slope[h];
            g_tab[tid * 16 + h * 2 + 1] = inter[h];
        }
    }
}

// =====================================================================
// GEMM body v3: 128 rows/block, 8 rows/thread; W in smem (64KB);
// A streamed via L1 (16-thread broadcast groups).
// =====================================================================
__device__ __forceinline__ void gemm_body(const float* __restrict__ A,
                                          const float* __restrict__ Wraw,
                                          float* __restrict__ Out,
                                          int mode, int row0)
{
    extern __shared__ float sm[];
    float* Wsm = sm;   // [128][128]

    const int tid = threadIdx.x;

    for (int i4 = tid; i4 < 4096; i4 += 256) {
        int d = i4 >> 5, c4 = (i4 & 31) * 4;
        float4 w;
        if (mode == 0) w = *(const float4*)(Wraw + (c4 >> 4) * (DIN * 16) + d * 16 + (c4 & 15));
        else           w = *(const float4*)(Wraw + d * 128 + c4);
        *(float4*)(Wsm + d * 128 + c4) = w;
    }
    __syncthreads();

    const int tx = tid & 15, ty = tid >> 4;
    const int ca = tx * 4;
    const int r0 = ty * 8;

    const float* Ab = A + (size_t)(row0 + r0) * 128;

    u64 acc2[8][4];
#pragma unroll
    for (int u = 0; u < 8; u++)
#pragma unroll
        for (int k = 0; k < 4; k++) acc2[u][k] = 0ull;

    for (int dc = 0; dc < 128; dc += 4) {
        float4 a4[8];
#pragma unroll
        for (int u = 0; u < 8; u++) a4[u] = *(const float4*)(Ab + (size_t)u * 128 + dc);
#pragma unroll
        for (int dd = 0; dd < 4; dd++) {
            ulonglong2 w0 = *(const ulonglong2*)(Wsm + (dc + dd) * 128 + ca);
            ulonglong2 w1 = *(const ulonglong2*)(Wsm + (dc + dd) * 128 + 64 + ca);
#pragma unroll
            for (int u = 0; u < 8; u++) {
                float a = (dd == 0) ? a4[u].x : (dd == 1) ? a4[u].y : (dd == 2) ? a4[u].z : a4[u].w;
                u64 a2 = pack2(a, a);
                acc2[u][0] = fma2(a2, w0.x, acc2[u][0]);
                acc2[u][1] = fma2(a2, w0.y, acc2[u][1]);
                acc2[u][2] = fma2(a2, w1.x, acc2[u][2]);
                acc2[u][3] = fma2(a2, w1.y, acc2[u][3]);
            }
        }
    }
#pragma unroll
    for (int u = 0; u < 8; u++) {
        float2 p0 = unpack2(acc2[u][0]), p1 = unpack2(acc2[u][1]);
        float2 p2 = unpack2(acc2[u][2]), p3 = unpack2(acc2[u][3]);
        float4 o0 = {p0.x, p0.y, p1.x, p1.y};
        float4 o1 = {p2.x, p2.y, p3.x, p3.y};
        const int row = row0 + r0 + u;
        if (mode == 0) {
            int h0 = ca >> 4, h1 = (64 + ca) >> 4;
            *(float4*)(Out + ((size_t)h0 * ROWS + row) * 16 + (ca & 15)) = o0;
            *(float4*)(Out + ((size_t)h1 * ROWS + row) * 16 + (ca & 15)) = o1;
        } else {
            float* orow = Out + (size_t)row * 128;
            *(float4*)(orow + ca)      = o0;
            *(float4*)(orow + 64 + ca) = o1;
        }
    }
}

// =====================================================================
// gemm_qkv + es fused launch: z<3 = QKV projections (128 rows/block);
// z==3 = (e,seg) pack pass (DRAM-bound, overlaps the FMA-bound gemms)
// =====================================================================
__global__ void __launch_bounds__(256, 2) gemm_qkv_seg_kernel(const float* __restrict__ q,
                                                              const float* __restrict__ hx,
                                                              const float* __restrict__ Wq,
                                                              const float* __restrict__ Wk,
                                                              const float* __restrict__ Wv,
                                                              const float* __restrict__ Ebm,
                                                              const int* __restrict__ mask)
{
    const int z = blockIdx.y;
    if (z == 3) {
        extern __shared__ float smf[];
        float* sB = smf;
        const int tid = threadIdx.x;
        for (int i = tid; i < 512; i += 256) sB[i] = g_breaks[i];
        __syncthreads();
        const size_t stride = 256 * 256;   // 256 blocks x 256 threads
        size_t base = (size_t)blockIdx.x * 256 + tid;
#pragma unroll 2
        for (int it = 0; it < 32; it++) {
            size_t v = base + (size_t)it * stride;   // float4 cell index
            float4 e4 = ((const float4*)Ebm)[v];
            int4   m4 = ((const int4*)mask)[v];
            const float ev[4] = {e4.x, e4.y, e4.z, e4.w};
            const int   mv[4] = {m4.x, m4.y, m4.z, m4.w};
            float sv[4];
#pragma unroll
            for (int p = 0; p < 4; p++) {
                float e = ev[p];
                int seg = 0;
#pragma unroll
                for (int st = 256; st >= 1; st >>= 1) {
                    int cnd = seg + st;
                    if (e >= sB[cnd - 1]) seg = cnd;
                }
                sv[p] = __int_as_float(seg | (mv[p] ? 0x8000 : 0));
            }
            float4* dst = (float4*)g_es + v * 2;
            dst[0] = make_float4(ev[0], sv[0], ev[1], sv[1]);
            dst[1] = make_float4(ev[2], sv[2], ev[3], sv[3]);
        }
        return;
    }
    const float* A = (z == 0) ? q : hx;
    const float* W = (z == 0) ? Wq : (z == 1) ? Wk : Wv;
    float* Out = (z == 0) ? g_Q : (z == 1) ? g_K : g_V;
    gemm_body(A, W, Out, 0, blockIdx.x * 128);
}

__global__ void __launch_bounds__(256, 2) gemm_out_kernel(const float* __restrict__ Wo,
                                                          float* __restrict__ Out)
{
    gemm_body(g_heads, Wo, Out, 1, blockIdx.x * 128);
}

// =====================================================================
// Fused attention v10: (e,seg) as single LDG.64; otherwise as v9.
// Block = (b, 64-row region, head). 512 threads, 2 blocks/SM.
// =====================================================================
__global__ void __launch_bounds__(512, 2)
attn_fused_kernel()
{
    extern __shared__ float sm[];
    float* SP   = sm;                 // [32][257]
    float* red  = SP + 8224;          // [16][32][20]
    float* sV   = red + 10240;        // [256][16]
    float* Qsm  = sV + 4096;          // [32][16]
    float* sT   = Qsm + 512;          // [304][2]
    float* sInv = sT + 608;           // [32]

    const int tid    = threadIdx.x;
    const int b      = blockIdx.y;
    const int itile0 = (blockIdx.x & 3) * 64;
    const int head   = blockIdx.x >> 2;

    const size_t hbase = (size_t)head * ROWS + (size_t)b * NN;

    const int warp = tid >> 5, lane = tid & 31;
    const int jq8 = warp & 7;
    const int jgl = jq8 * 32 + lane;
    const int rh  = warp >> 3;

    u64 K2[8];
    {
        const ulonglong2* Kg = (const ulonglong2*)(g_K + (hbase + jgl) * 16);
#pragma unroll
        for (int qq = 0; qq < 4; qq++) {
            ulonglong2 kv = Kg[qq];
            K2[qq * 2]     = kv.x;
            K2[qq * 2 + 1] = kv.y;
        }
    }

    {
        const float4* Vg = (const float4*)(g_V + hbase * 16);
#pragma unroll
        for (int p = 0; p < 2; p++) {
            int q4 = tid + 512 * p;
            *(float4*)(sV + q4 * 4) = Vg[q4];
        }
        if (tid < 304) {
            sT[tid * 2]     = g_tab[tid * 16 + head * 2];
            sT[tid * 2 + 1] = g_tab[tid * 16 + head * 2 + 1];
        }
    }

    for (int tile = 0; tile < 2; tile++) {
        const int itile = itile0 + tile * 32;

        __syncthreads();
        if (tid < 128) {
            float4 qv = *(const float4*)(g_Q + (hbase + itile) * 16 + tid * 4);
            qv.x *= NORMC; qv.y *= NORMC; qv.z *= NORMC; qv.w *= NORMC;
            *(float4*)(Qsm + tid * 4) = qv;
        }
        __syncthreads();

        // ---- P1: SP = bias(e) + Q.K  (single (e,seg) LDG.64 per row)
        {
            const float2* esp = g_es + (size_t)(b * NN + itile) * NN + jgl;
            const int rbase = rh * 16;

            float2 es_nxt = esp[(size_t)rbase * NN];

#pragma unroll 4
            for (int rr = 0; rr < 16; rr++) {
                const int r = rbase + rr;
                float2 es_cur = es_nxt;
                if (rr < 15) es_nxt = esp[(size_t)(r + 1) * NN];

                const ulonglong2* qp = (const ulonglong2*)(Qsm + r * 16);
                ulonglong2 qa = qp[0], qb = qp[1], qc = qp[2], qd = qp[3];
                u64 d2 = 0ull;
                d2 = fma2(qa.x, K2[0], d2); d2 = fma2(qa.y, K2[1], d2);
                d2 = fma2(qb.x, K2[2], d2); d2 = fma2(qb.y, K2[3], d2);
                d2 = fma2(qc.x, K2[4], d2); d2 = fma2(qc.y, K2[5], d2);
                d2 = fma2(qd.x, K2[6], d2); d2 = fma2(qd.y, K2[7], d2);
                float2 df = unpack2(d2);
                float d = df.x + df.y;

                unsigned int sbits = __float_as_uint(es_cur.y);
                int seg = sbits & 0x7fff;
                float2 t = *(const float2*)(sT + seg * 2);
                float bias = (sbits & 0x8000) ? -INFINITY : fmaf(t.x, es_cur.x, t.y);
                SP[r * SPS + jgl] = bias + d;
            }
        }
        __syncthreads();

        // ---- P2: softmax (unnormalized exp; inv per row)
        {
#pragma unroll
            for (int rr = 0; rr < 2; rr++) {
                const int r = warp * 2 + rr;
                float v[8];
#pragma unroll
                for (int m = 0; m < 8; m++) v[m] = SP[r * SPS + lane + 32 * m];
                float mx = v[0];
#pragma unroll
                for (int m = 1; m < 8; m++) mx = fmaxf(mx, v[m]);
#pragma unroll
                for (int o = 16; o > 0; o >>= 1) mx = fmaxf(mx, __shfl_xor_sync(0xffffffffu, mx, o));
                float s = 0.f;
#pragma unroll
                for (int m = 0; m < 8; m++) { v[m] = __expf(v[m] - mx); s += v[m]; }
#pragma unroll
                for (int o = 16; o > 0; o >>= 1) s += __shfl_xor_sync(0xffffffffu, s, o);
                if (lane == 0) sInv[r] = 1.f / s;
#pragma unroll
                for (int m = 0; m < 8; m++) SP[r * SPS + lane + 32 * m] = v[m];
            }
        }
        __syncthreads();

        // ---- P3: AV, (2-row, 8-v) lanes
        {
            const int j0 = warp * 16;
            const int r2 = (lane & 15) * 2;
            const int v0 = (lane >> 4) * 8;
            u64 acc[8];
#pragma unroll
            for (int v = 0; v < 8; v++) acc[v] = 0ull;
#pragma unroll
            for (int jj = 0; jj < 16; jj++) {
                const int j = j0 + jj;
                float pa = SP[r2 * SPS + j];
                float pb = SP[(r2 + 1) * SPS + j];
                u64 pa2 = pack2(pa, pa);
                u64 pb2 = pack2(pb, pb);
                const ulonglong2* vp = (const ulonglong2*)(sV + j * 16 + v0);
                ulonglong2 va = vp[0], vb = vp[1];
                acc[0] = fma2(pa2, va.x, acc[0]); acc[1] = fma2(pa2, va.y, acc[1]);
                acc[2] = fma2(pa2, vb.x, acc[2]); acc[3] = fma2(pa2, vb.y, acc[3]);
                acc[4] = fma2(pb2, va.x, acc[4]); acc[5] = fma2(pb2, va.y, acc[5]);
                acc[6] = fma2(pb2, vb.x, acc[6]); acc[7] = fma2(pb2, vb.y, acc[7]);
            }
            ulonglong2* rpa = (ulonglong2*)(red + (warp * 32 + r2) * RST + v0);
            ulonglong2* rpb = (ulonglong2*)(red + (warp * 32 + r2 + 1) * RST + v0);
            rpa[0] = make_ulonglong2(acc[0], acc[1]);
            rpa[1] = make_ulonglong2(acc[2], acc[3]);
            rpb[0] = make_ulonglong2(acc[4], acc[5]);
            rpb[1] = make_ulonglong2(acc[6], acc[7]);
        }
        __syncthreads();

        // ---- P4
        if (tid < 256) {
            const int r = tid >> 3, vp = tid & 7;
            u64 s = 0ull;
#pragma unroll
            for (int jq = 0; jq < 16; jq++)
                s = addp2(s, *(const u64*)(red + (jq * 32 + r) * RST + vp * 2));
            float inv = sInv[r];
            float2 f = unpack2(s);
            f.x *= inv; f.y *= inv;
            *(float2*)(g_heads + (size_t)(b * NN + itile + r) * HK + head * 16 + vp * 2) = f;
        }
    }
}

// =====================================================================
// host launcher
// =====================================================================
extern "C" void kernel_launch(void* const* d_in, const int* in_sizes, int n_in,
                              void* d_out, int out_size)
{
    (void)in_sizes; (void)n_in; (void)out_size;
    const float* q    = (const float*)d_in[0];
    const float* hx   = (const float*)d_in[1];
    const int*   mask = (const int*)d_in[2];
    const float* edge = (const float*)d_in[3];
    const float* Wq   = (const float*)d_in[4];
    const float* Wk   = (const float*)d_in[5];
    const float* Wv   = (const float*)d_in[6];
    const float* Wo   = (const float*)d_in[7];
    const float* mw1  = (const float*)d_in[8];
    const float* mb1  = (const float*)d_in[9];
    const float* mw2  = (const float*)d_in[10];
    const float* mb2  = (const float*)d_in[11];
    const float* mw3  = (const float*)d_in[12];
    const float* mb3  = (const float*)d_in[13];

    const int smem_gemm = 128 * 128 * 4;   // 65,536 B -> 2 blocks/SM
    const int smem_attn = 23712 * 4;       // 94,848 B -> 2 blocks/SM

    cudaFuncSetAttribute(gemm_qkv_seg_kernel, cudaFuncAttributeMaxDynamicSharedMemorySize, smem_gemm);
    cudaFuncSetAttribute(gemm_out_kernel,     cudaFuncAttributeMaxDynamicSharedMemorySize, smem_gemm);
    cudaFuncSetAttribute(attn_fused_kernel,   cudaFuncAttributeMaxDynamicSharedMemorySize, smem_attn);

    pwl_build_kernel<<<1, 512>>>(mw1, mb1, mw2, mb2, mw3, mb3);

    // QKV projections (128 rows/block) + (e,seg) pack in one launch
    gemm_qkv_seg_kernel<<<dim3(ROWS / 128, 4), 256, smem_gemm>>>(q, hx, Wq, Wk, Wv, edge, mask);

    attn_fused_kernel<<<dim3(32, BB), 512, smem_attn>>>();

    gemm_out_kernel<<<ROWS / 128, 256, smem_gemm>>>(Wo, (float*)d_out);
}